// round 1
// baseline (speedup 1.0000x reference)
#include <cuda_runtime.h>
#include <cuda_bf16.h>
#include <cstdint>

#define N_ 50000
#define F_ 128
#define E_ 800000
#define K_ 64
#define L_ 3

// Scratch buffers (static device globals: allowed, no runtime allocation)
__device__ float g_xa[(size_t)N_ * F_];     // ssp(x), later reused as y
__device__ float g_m[(size_t)N_ * F_];      // xi, then m
__device__ float g_xjall[(size_t)N_ * F_];  // ssp(xa@Wj+bj)
__device__ float g_xj[(size_t)N_ * F_];     // segment sum accumulator
__device__ float g_y[(size_t)N_ * F_];      // residual temp

__device__ __forceinline__ float ssp(float v) {
    // softplus(v) - ln2, numerically stable
    float ax = fabsf(v);
    float sp = fmaxf(v, 0.0f) + log1pf(__expf(-ax));
    return sp - 0.69314718055994530942f;
}

__device__ __forceinline__ float4 ssp4(float4 v) {
    v.x = ssp(v.x); v.y = ssp(v.y); v.z = ssp(v.z); v.w = ssp(v.w);
    return v;
}

// ---------------------------------------------------------------------------
// prep: xa = ssp(x); xj = 0
// ---------------------------------------------------------------------------
__global__ void prep_kernel(const float* __restrict__ x,
                            float* __restrict__ xa,
                            float* __restrict__ xj) {
    int i = blockIdx.x * blockDim.x + threadIdx.x;
    if (i < N_ * F_ / 4) {
        float4 v = reinterpret_cast<const float4*>(x)[i];
        reinterpret_cast<float4*>(xa)[i] = ssp4(v);
        reinterpret_cast<float4*>(xj)[i] = make_float4(0.f, 0.f, 0.f, 0.f);
    }
}

// m += b  (m = xi + xj, in place into g_m)
__global__ void add_kernel(float* __restrict__ m, const float* __restrict__ b) {
    int i = blockIdx.x * blockDim.x + threadIdx.x;
    if (i < N_ * F_ / 4) {
        float4 a = reinterpret_cast<float4*>(m)[i];
        float4 c = reinterpret_cast<const float4*>(b)[i];
        a.x += c.x; a.y += c.y; a.z += c.z; a.w += c.w;
        reinterpret_cast<float4*>(m)[i] = a;
    }
}

// ---------------------------------------------------------------------------
// Node GEMM: C = epilogue( [ssp?](A) @ W + bias )  for F=128
// Block: 64 rows x 128 cols. 256 threads, thread = 8 rows x 4 cols.
// Full A-tile (64x128) and full W (128x128) staged in smem.
// EP: 0 -> C = r (+out_act), 1 -> C = C + r, 2 -> C = u*x + r
// ---------------------------------------------------------------------------
template <bool IN_ACT, bool OUT_ACT, int EP>
__global__ __launch_bounds__(256, 2)
void gemm128_kernel(const float* __restrict__ A, const float* __restrict__ W,
                    const float* __restrict__ bias, float* __restrict__ C,
                    const float* __restrict__ x, const float* __restrict__ u,
                    int n) {
    extern __shared__ float sm[];
    float* As = sm;                  // [64][128]
    float* Ws = sm + 64 * 128;       // [128][128]

    int tid = threadIdx.x;
    int row0 = blockIdx.x * 64;

    // stage W: 4096 float4
    const float4* W4 = reinterpret_cast<const float4*>(W);
    float4* Ws4 = reinterpret_cast<float4*>(Ws);
#pragma unroll
    for (int i = 0; i < 16; ++i) Ws4[tid + i * 256] = W4[tid + i * 256];

    // stage A tile: 2048 float4 (guard rows, optional input activation)
    const float4* A4 = reinterpret_cast<const float4*>(A);
    float4* As4 = reinterpret_cast<float4*>(As);
#pragma unroll
    for (int i = 0; i < 8; ++i) {
        int idx = tid + i * 256;           // 0..2047
        int r = idx >> 5;                  // row in tile
        int k4 = idx & 31;
        float4 v = make_float4(0.f, 0.f, 0.f, 0.f);
        if (row0 + r < n) v = A4[(size_t)(row0 + r) * 32 + k4];
        if (IN_ACT) v = ssp4(v);
        As4[idx] = v;
    }
    __syncthreads();

    int tx = tid & 31;      // column group: cols tx*4 .. tx*4+3
    int ty = tid >> 5;      // row group: rows ty*8 .. ty*8+7
    int r0 = ty * 8;

    float acc[8][4];
#pragma unroll
    for (int i = 0; i < 8; ++i)
#pragma unroll
        for (int j = 0; j < 4; ++j) acc[i][j] = 0.f;

#pragma unroll 4
    for (int k4 = 0; k4 < 32; ++k4) {
        float4 w0 = Ws4[(k4 * 4 + 0) * 32 + tx];
        float4 w1 = Ws4[(k4 * 4 + 1) * 32 + tx];
        float4 w2 = Ws4[(k4 * 4 + 2) * 32 + tx];
        float4 w3 = Ws4[(k4 * 4 + 3) * 32 + tx];
#pragma unroll
        for (int i = 0; i < 8; ++i) {
            float4 a = As4[(r0 + i) * 32 + k4];
            acc[i][0] += a.x * w0.x; acc[i][1] += a.x * w0.y;
            acc[i][2] += a.x * w0.z; acc[i][3] += a.x * w0.w;
            acc[i][0] += a.y * w1.x; acc[i][1] += a.y * w1.y;
            acc[i][2] += a.y * w1.z; acc[i][3] += a.y * w1.w;
            acc[i][0] += a.z * w2.x; acc[i][1] += a.z * w2.y;
            acc[i][2] += a.z * w2.z; acc[i][3] += a.z * w2.w;
            acc[i][0] += a.w * w3.x; acc[i][1] += a.w * w3.y;
            acc[i][2] += a.w * w3.z; acc[i][3] += a.w * w3.w;
        }
    }

    float4 b4 = reinterpret_cast<const float4*>(bias)[tx];
    float4* C4 = reinterpret_cast<float4*>(C);

#pragma unroll
    for (int i = 0; i < 8; ++i) {
        int r = row0 + r0 + i;
        if (r >= n) break;
        float4 v;
        v.x = acc[i][0] + b4.x; v.y = acc[i][1] + b4.y;
        v.z = acc[i][2] + b4.z; v.w = acc[i][3] + b4.w;
        if constexpr (EP == 1) {
            float4 old = C4[(size_t)r * 32 + tx];
            v.x += old.x; v.y += old.y; v.z += old.z; v.w += old.w;
        }
        if constexpr (EP == 2) {
            float4 xv = reinterpret_cast<const float4*>(x)[(size_t)r * 32 + tx];
            float4 u4 = reinterpret_cast<const float4*>(u)[tx];
            v.x += u4.x * xv.x; v.y += u4.y * xv.y;
            v.z += u4.z * xv.z; v.w += u4.w * xv.w;
        }
        if constexpr (OUT_ACT) v = ssp4(v);
        C4[(size_t)r * 32 + tx] = v;
    }
}

// ---------------------------------------------------------------------------
// Edge kernel: for each edge e:
//   g[e,:] = rbf[e,:] @ Wk2f           (K=64 -> F=128, Wk2f in smem)
//   msg    = g * xjall[idx_j[e], :]
//   xj[idx_i[e], :] += msg             (run-length accumulate, idx_i sorted)
// Block: 512 edges, 256 threads. Thread = 8 columns, sequential 32-edge range.
// ---------------------------------------------------------------------------
__global__ __launch_bounds__(256, 2)
void edge_kernel(const float* __restrict__ rbf, const float* __restrict__ Wk2f,
                 const float* __restrict__ xjall, const int* __restrict__ ii,
                 const int* __restrict__ jj, float* __restrict__ xj) {
    extern __shared__ float sm[];
    float* Ws = sm;                   // [64][128] = 8192 floats
    float* Rs = sm + 8192;            // [256][64] = 16384 floats

    int tid = threadIdx.x;

    // stage Wk2f: 2048 float4
    const float4* W4g = reinterpret_cast<const float4*>(Wk2f);
    float4* Ws4 = reinterpret_cast<float4*>(Ws);
#pragma unroll
    for (int i = 0; i < 8; ++i) Ws4[tid + i * 256] = W4g[tid + i * 256];

    int tx = tid & 15;        // column group: cols tx*8 .. tx*8+7
    int grp = tid >> 4;       // 16 edge groups, 32 contiguous edges each
    int c0 = tx * 8;
    long cb = (long)blockIdx.x * 512;

    float4* Rs4 = reinterpret_cast<float4*>(Rs);
    const float4* rbf4 = reinterpret_cast<const float4*>(rbf);

    int cur_i = -1;
    float racc[8];
#pragma unroll
    for (int q = 0; q < 8; ++q) racc[q] = 0.f;

    for (int tile = 0; tile < 2; ++tile) {
        __syncthreads();
        // stage rbf for 256 edges (16 per group): 4096 float4
#pragma unroll
        for (int t = 0; t < 16; ++t) {
            int idx = tid + t * 256;       // 0..4095
            int r = idx >> 4;              // staged row 0..255
            int k4 = idx & 15;
            int gr = r >> 4;
            int s = r & 15;
            long e = cb + (long)gr * 32 + tile * 16 + s;
            float4 v = make_float4(0.f, 0.f, 0.f, 0.f);
            if (e < E_) v = rbf4[e * 16 + k4];
            Rs4[r * 16 + k4] = v;
        }
        __syncthreads();

        for (int s = 0; s < 16; ++s) {
            long e = cb + (long)grp * 32 + tile * 16 + s;
            if (e >= E_) continue;
            int i = __ldg(ii + e);
            int j = __ldg(jj + e);
            const float4* xv4 =
                reinterpret_cast<const float4*>(xjall + (size_t)j * 128 + c0);
            float4 xv0 = __ldg(xv4);
            float4 xv1 = __ldg(xv4 + 1);

            float g[8];
#pragma unroll
            for (int q = 0; q < 8; ++q) g[q] = 0.f;

            int rrow = grp * 16 + s;
#pragma unroll
            for (int k4 = 0; k4 < 16; ++k4) {
                float4 rb = Rs4[rrow * 16 + k4];
#pragma unroll
                for (int kk = 0; kk < 4; ++kk) {
                    float rv = (kk == 0) ? rb.x : (kk == 1) ? rb.y
                              : (kk == 2) ? rb.z : rb.w;
                    float4 wa = Ws4[(k4 * 4 + kk) * 32 + tx * 2];
                    float4 wb = Ws4[(k4 * 4 + kk) * 32 + tx * 2 + 1];
                    g[0] += rv * wa.x; g[1] += rv * wa.y;
                    g[2] += rv * wa.z; g[3] += rv * wa.w;
                    g[4] += rv * wb.x; g[5] += rv * wb.y;
                    g[6] += rv * wb.z; g[7] += rv * wb.w;
                }
            }

            float val[8];
            val[0] = g[0] * xv0.x; val[1] = g[1] * xv0.y;
            val[2] = g[2] * xv0.z; val[3] = g[3] * xv0.w;
            val[4] = g[4] * xv1.x; val[5] = g[5] * xv1.y;
            val[6] = g[6] * xv1.z; val[7] = g[7] * xv1.w;

            if (i != cur_i) {
                if (cur_i >= 0) {
                    float* dst = xj + (size_t)cur_i * 128 + c0;
#pragma unroll
                    for (int q = 0; q < 8; ++q) atomicAdd(dst + q, racc[q]);
                }
                cur_i = i;
#pragma unroll
                for (int q = 0; q < 8; ++q) racc[q] = val[q];
            } else {
#pragma unroll
                for (int q = 0; q < 8; ++q) racc[q] += val[q];
            }
        }
    }
    if (cur_i >= 0) {
        float* dst = xj + (size_t)cur_i * 128 + c0;
#pragma unroll
        for (int q = 0; q < 8; ++q) atomicAdd(dst + q, racc[q]);
    }
}

// ---------------------------------------------------------------------------
// Launch
// ---------------------------------------------------------------------------
extern "C" void kernel_launch(void* const* d_in, const int* in_sizes, int n_in,
                              void* d_out, int out_size) {
    const float* x    = (const float*)d_in[0];
    const float* rbf  = (const float*)d_in[1];
    const float* Wk2f = (const float*)d_in[2];
    const float* Wi   = (const float*)d_in[3];
    const float* bi   = (const float*)d_in[4];
    const float* Wj   = (const float*)d_in[5];
    const float* bj   = (const float*)d_in[6];
    const float* Wr1  = (const float*)d_in[7];
    const float* br1  = (const float*)d_in[8];
    const float* Wr2  = (const float*)d_in[9];
    const float* br2  = (const float*)d_in[10];
    const float* Wf   = (const float*)d_in[11];
    const float* bfb  = (const float*)d_in[12];
    const float* u    = (const float*)d_in[13];
    const int* idx_i  = (const int*)d_in[14];
    const int* idx_j  = (const int*)d_in[15];
    float* out = (float*)d_out;

    void *p_xa, *p_m, *p_xjall, *p_xj, *p_y;
    cudaGetSymbolAddress(&p_xa, g_xa);
    cudaGetSymbolAddress(&p_m, g_m);
    cudaGetSymbolAddress(&p_xjall, g_xjall);
    cudaGetSymbolAddress(&p_xj, g_xj);
    cudaGetSymbolAddress(&p_y, g_y);
    float* xa = (float*)p_xa;
    float* m = (float*)p_m;
    float* xjall = (float*)p_xjall;
    float* xj = (float*)p_xj;
    float* y = (float*)p_y;

    const int SMEM = (64 * 128 + 128 * 128) * 4;  // 98304 B (same for edge)
    cudaFuncSetAttribute(gemm128_kernel<false, true, 0>,
                         cudaFuncAttributeMaxDynamicSharedMemorySize, SMEM);
    cudaFuncSetAttribute(gemm128_kernel<true, true, 0>,
                         cudaFuncAttributeMaxDynamicSharedMemorySize, SMEM);
    cudaFuncSetAttribute(gemm128_kernel<false, false, 1>,
                         cudaFuncAttributeMaxDynamicSharedMemorySize, SMEM);
    cudaFuncSetAttribute(gemm128_kernel<true, false, 2>,
                         cudaFuncAttributeMaxDynamicSharedMemorySize, SMEM);
    cudaFuncSetAttribute(edge_kernel,
                         cudaFuncAttributeMaxDynamicSharedMemorySize, SMEM);

    int ew_blocks = (N_ * F_ / 4 + 255) / 256;
    int gemm_blocks = (N_ + 63) / 64;
    int edge_blocks = (E_ + 511) / 512;

    // xa = ssp(x); xj = 0
    prep_kernel<<<ew_blocks, 256>>>(x, xa, xj);
    // xi (-> m) = ssp(xa @ Wi + bi)
    gemm128_kernel<false, true, 0><<<gemm_blocks, 256, SMEM>>>(
        xa, Wi, bi, m, nullptr, nullptr, N_);
    // xjall = ssp(xa @ Wj + bj)
    gemm128_kernel<false, true, 0><<<gemm_blocks, 256, SMEM>>>(
        xa, Wj, bj, xjall, nullptr, nullptr, N_);
    // xj += segment_sum(g * xjall[idx_j], idx_i)
    edge_kernel<<<edge_blocks, 256, SMEM>>>(rbf, Wk2f, xjall, idx_i, idx_j, xj);
    // m = xi + xj
    add_kernel<<<ew_blocks, 256>>>(m, xj);

    // residual blocks
    for (int l = 0; l < L_; ++l) {
        // y = ssp(ssp(m) @ Wr1[l] + br1[l])
        gemm128_kernel<true, true, 0><<<gemm_blocks, 256, SMEM>>>(
            m, Wr1 + (size_t)l * F_ * F_, br1 + (size_t)l * F_, y,
            nullptr, nullptr, N_);
        // m = m + y @ Wr2[l] + br2[l]
        gemm128_kernel<false, false, 1><<<gemm_blocks, 256, SMEM>>>(
            y, Wr2 + (size_t)l * F_ * F_, br2 + (size_t)l * F_, m,
            nullptr, nullptr, N_);
    }

    // out = u * x + ssp(m) @ Wf + bf
    gemm128_kernel<true, false, 2><<<gemm_blocks, 256, SMEM>>>(
        m, Wf, bfb, out, x, u, N_);
}

// round 3
// speedup vs baseline: 2.1487x; 2.1487x over previous
#include <cuda_runtime.h>
#include <cstdint>

#define N_ 50000
#define F_ 128
#define E_ 800000
#define K_ 64
#define L_ 3

using u64 = unsigned long long;

// Scratch (static device globals — no runtime allocation)
__device__ float g_xa[(size_t)N_ * F_];     // ssp(x)
__device__ float g_m[(size_t)N_ * F_];      // xi, then m (edge kernel adds into it)
__device__ float g_xjall[(size_t)N_ * F_];  // ssp(xa@Wj+bj)
__device__ float g_y[(size_t)N_ * F_];      // residual temp
// Pair-packed transposed weights: [mat][k2][c] as (W[2k2][c], W[2k2+1][c])
__device__ u64 g_wt2[9 * 64 * 128];         // 9 node matrices, K=128 -> 64 k2 rows
__device__ u64 g_wk2f2[32 * 128];           // Wk2f, K=64 -> 32 k2 rows

__device__ __forceinline__ float ssp(float v) {
    float ax = fabsf(v);
    float sp = fmaxf(v, 0.0f) + log1pf(__expf(-ax));
    return sp - 0.69314718055994530942f;
}
__device__ __forceinline__ float4 ssp4(float4 v) {
    v.x = ssp(v.x); v.y = ssp(v.y); v.z = ssp(v.z); v.w = ssp(v.w);
    return v;
}

// packed f32x2 FMA: d = a*b + c (lane-wise on the two fp32 halves)
__device__ __forceinline__ u64 ffma2(u64 a, u64 b, u64 c) {
    u64 d;
    asm("fma.rn.f32x2 %0, %1, %2, %3;" : "=l"(d) : "l"(a), "l"(b), "l"(c));
    return d;
}
__device__ __forceinline__ float pairsum(u64 v) {
    return __uint_as_float((unsigned)v) + __uint_as_float((unsigned)(v >> 32));
}

// ---------------------------------------------------------------------------
// Pack weights: W[K][128] row-major -> out[k2*128 + c] = (W[2k2][c], W[2k2+1][c])
// ---------------------------------------------------------------------------
__global__ void pack_kernel(const float* __restrict__ W, u64* __restrict__ out,
                            int halfK) {
    int i = blockIdx.x * blockDim.x + threadIdx.x;
    if (i < halfK * 128) {
        int k2 = i >> 7, c = i & 127;
        unsigned lo = __float_as_uint(W[(2 * k2) * 128 + c]);
        unsigned hi = __float_as_uint(W[(2 * k2 + 1) * 128 + c]);
        out[i] = ((u64)hi << 32) | lo;
    }
}

// xa = ssp(x)
__global__ void prep_kernel(const float* __restrict__ x, float* __restrict__ xa) {
    int i = blockIdx.x * blockDim.x + threadIdx.x;
    if (i < N_ * F_ / 4) {
        float4 v = reinterpret_cast<const float4*>(x)[i];
        reinterpret_cast<float4*>(xa)[i] = ssp4(v);
    }
}

// ---------------------------------------------------------------------------
// Node GEMM (f32x2): C = epilogue( [ssp?](A) @ W + bias ), F=128 (K=128!).
// Block 64 rows x 128 cols, 256 threads = 8 row-groups x 32 col-groups.
// Accumulators are k-split f32x2 pairs; 32 k-iterations x 4 k each = 128.
// EP: 0 -> r, 1 -> C+r, 2 -> u*x + r
// ---------------------------------------------------------------------------
template <bool IN_ACT, bool OUT_ACT, int EP>
__global__ __launch_bounds__(256, 2)
void gemm128_f2(const float* __restrict__ A, const u64* __restrict__ Wt2,
                const float* __restrict__ bias, float* __restrict__ C,
                const float* __restrict__ x, const float* __restrict__ u,
                int n) {
    extern __shared__ __align__(16) char smraw[];
    u64* Ws = reinterpret_cast<u64*>(smraw);            // [64 k2][128 c] = 64KB
    float* As = reinterpret_cast<float*>(smraw + 65536);  // [64 r][128 k] = 32KB

    int tid = threadIdx.x;
    int row0 = blockIdx.x * 64;

    // stage packed W: 8192 u64 = 4096 ulonglong2
    {
        const ulonglong2* src = reinterpret_cast<const ulonglong2*>(Wt2);
        ulonglong2* dst = reinterpret_cast<ulonglong2*>(Ws);
#pragma unroll
        for (int i = 0; i < 16; ++i) dst[tid + i * 256] = src[tid + i * 256];
    }
    // stage A tile (guarded, optional ssp)
    {
        const float4* A4 = reinterpret_cast<const float4*>(A);
        float4* As4 = reinterpret_cast<float4*>(As);
#pragma unroll
        for (int i = 0; i < 8; ++i) {
            int idx = tid + i * 256;       // 0..2047
            int r = idx >> 5;
            int k4 = idx & 31;
            float4 v = make_float4(0.f, 0.f, 0.f, 0.f);
            if (row0 + r < n) v = A4[(size_t)(row0 + r) * 32 + k4];
            if (IN_ACT) v = ssp4(v);
            As4[idx] = v;
        }
    }
    __syncthreads();

    int tx = tid & 31;       // col group: cols tx*4..tx*4+3
    int ty = tid >> 5;       // row group: rows ty*8..ty*8+7
    int r0 = ty * 8;

    u64 acc[8][4];
#pragma unroll
    for (int i = 0; i < 8; ++i)
#pragma unroll
        for (int j = 0; j < 4; ++j) acc[i][j] = 0ull;

    const ulonglong2* As2 = reinterpret_cast<const ulonglong2*>(As);
    const ulonglong2* Ws2 = reinterpret_cast<const ulonglong2*>(Ws);

#pragma unroll 4
    for (int kk = 0; kk < 32; ++kk) {   // 4 k per iter x 32 = full K=128
        // W pairs for k2 = 2kk (wa*) and k2 = 2kk+1 (wb*), 4 cols each
        ulonglong2 wa0 = Ws2[(2 * kk) * 64 + tx * 2];
        ulonglong2 wa1 = Ws2[(2 * kk) * 64 + tx * 2 + 1];
        ulonglong2 wb0 = Ws2[(2 * kk + 1) * 64 + tx * 2];
        ulonglong2 wb1 = Ws2[(2 * kk + 1) * 64 + tx * 2 + 1];
#pragma unroll
        for (int i = 0; i < 8; ++i) {
            ulonglong2 a = As2[(r0 + i) * 32 + kk];  // k = 4kk..4kk+3
            acc[i][0] = ffma2(a.x, wa0.x, acc[i][0]);
            acc[i][1] = ffma2(a.x, wa0.y, acc[i][1]);
            acc[i][2] = ffma2(a.x, wa1.x, acc[i][2]);
            acc[i][3] = ffma2(a.x, wa1.y, acc[i][3]);
            acc[i][0] = ffma2(a.y, wb0.x, acc[i][0]);
            acc[i][1] = ffma2(a.y, wb0.y, acc[i][1]);
            acc[i][2] = ffma2(a.y, wb1.x, acc[i][2]);
            acc[i][3] = ffma2(a.y, wb1.y, acc[i][3]);
        }
    }

    float4 b4 = reinterpret_cast<const float4*>(bias)[tx];
    float4* C4 = reinterpret_cast<float4*>(C);

#pragma unroll
    for (int i = 0; i < 8; ++i) {
        int r = row0 + r0 + i;
        if (r >= n) break;
        float4 v;
        v.x = pairsum(acc[i][0]) + b4.x;
        v.y = pairsum(acc[i][1]) + b4.y;
        v.z = pairsum(acc[i][2]) + b4.z;
        v.w = pairsum(acc[i][3]) + b4.w;
        if constexpr (EP == 1) {
            float4 old = C4[(size_t)r * 32 + tx];
            v.x += old.x; v.y += old.y; v.z += old.z; v.w += old.w;
        }
        if constexpr (EP == 2) {
            float4 xv = reinterpret_cast<const float4*>(x)[(size_t)r * 32 + tx];
            float4 u4 = reinterpret_cast<const float4*>(u)[tx];
            v.x += u4.x * xv.x; v.y += u4.y * xv.y;
            v.z += u4.z * xv.z; v.w += u4.w * xv.w;
        }
        if constexpr (OUT_ACT) v = ssp4(v);
        C4[(size_t)r * 32 + tx] = v;
    }
}

// ---------------------------------------------------------------------------
// Edge kernel (f32x2, register-blocked over edges):
//   g = rbf[e,:] @ Wk2f ; msg = g * xjall[idx_j[e]] ; m[idx_i[e]] += msg
// Block: 512 edges (8 tiles of 64). 256 threads = 8 warps (8 edges each)
// x 32 col-groups (4 cols each). K=64 -> 16 k-iterations.
// ---------------------------------------------------------------------------
__global__ __launch_bounds__(256, 2)
void edge_f2(const float* __restrict__ rbf, const u64* __restrict__ Wt2,
             const float* __restrict__ xjall, const int* __restrict__ ii,
             const int* __restrict__ jj, float* __restrict__ mout) {
    extern __shared__ __align__(16) char smraw[];
    u64* Ws = reinterpret_cast<u64*>(smraw);             // [32 k2][128 c] = 32KB
    float* rs = reinterpret_cast<float*>(smraw + 32768);   // [64 e][64 k] = 16KB

    int tid = threadIdx.x;

    // stage packed Wk2f: 4096 u64 = 2048 ulonglong2
    {
        const ulonglong2* src = reinterpret_cast<const ulonglong2*>(Wt2);
        ulonglong2* dst = reinterpret_cast<ulonglong2*>(Ws);
#pragma unroll
        for (int i = 0; i < 8; ++i) dst[tid + i * 256] = src[tid + i * 256];
    }

    int tx = tid & 31;     // col group: cols tx*4..tx*4+3
    int eg = tid >> 5;     // warp id = edge group (8 contiguous edges)
    int c0 = tx * 4;
    long base = (long)blockIdx.x * 512;

    const float4* rbf4 = reinterpret_cast<const float4*>(rbf);
    float4* rs4 = reinterpret_cast<float4*>(rs);
    const ulonglong2* rs2 = reinterpret_cast<const ulonglong2*>(rs);
    const ulonglong2* Ws2 = reinterpret_cast<const ulonglong2*>(Ws);

    int cur_i = -1;
    float racc[4] = {0.f, 0.f, 0.f, 0.f};

    for (int t = 0; t < 8; ++t) {
        __syncthreads();
        // stage rbf for 64 edges: 1024 float4
#pragma unroll
        for (int s = 0; s < 4; ++s) {
            int idx = tid + s * 256;     // 0..1023
            int er = idx >> 4;           // local edge 0..63
            int k4 = idx & 15;
            long e = base + t * 64 + er;
            float4 v = make_float4(0.f, 0.f, 0.f, 0.f);
            if (e < E_) v = rbf4[e * 16 + k4];
            rs4[er * 16 + k4] = v;
        }
        __syncthreads();

        u64 acc[8][4];
#pragma unroll
        for (int el = 0; el < 8; ++el)
#pragma unroll
            for (int j = 0; j < 4; ++j) acc[el][j] = 0ull;

#pragma unroll 2
        for (int kk = 0; kk < 16; ++kk) {   // 4 k per iter x 16 = K=64
            ulonglong2 wa0 = Ws2[(2 * kk) * 64 + tx * 2];
            ulonglong2 wa1 = Ws2[(2 * kk) * 64 + tx * 2 + 1];
            ulonglong2 wb0 = Ws2[(2 * kk + 1) * 64 + tx * 2];
            ulonglong2 wb1 = Ws2[(2 * kk + 1) * 64 + tx * 2 + 1];
#pragma unroll
            for (int el = 0; el < 8; ++el) {
                ulonglong2 a = rs2[(eg * 8 + el) * 16 + kk];  // broadcast
                acc[el][0] = ffma2(a.x, wa0.x, acc[el][0]);
                acc[el][1] = ffma2(a.x, wa0.y, acc[el][1]);
                acc[el][2] = ffma2(a.x, wa1.x, acc[el][2]);
                acc[el][3] = ffma2(a.x, wa1.y, acc[el][3]);
                acc[el][0] = ffma2(a.y, wb0.x, acc[el][0]);
                acc[el][1] = ffma2(a.y, wb0.y, acc[el][1]);
                acc[el][2] = ffma2(a.y, wb1.x, acc[el][2]);
                acc[el][3] = ffma2(a.y, wb1.y, acc[el][3]);
            }
        }

        // epilogue: gather + gate + run-length scatter (idx_i sorted)
#pragma unroll
        for (int el = 0; el < 8; ++el) {
            long e = base + t * 64 + eg * 8 + el;
            if (e >= E_) break;
            int i = __ldg(ii + e);
            int j = __ldg(jj + e);
            float4 xv = __ldg(reinterpret_cast<const float4*>(
                                  xjall + (size_t)j * 128) + tx);
            float v0 = pairsum(acc[el][0]) * xv.x;
            float v1 = pairsum(acc[el][1]) * xv.y;
            float v2 = pairsum(acc[el][2]) * xv.z;
            float v3 = pairsum(acc[el][3]) * xv.w;
            if (i != cur_i) {
                if (cur_i >= 0) {
                    float* dst = mout + (size_t)cur_i * 128 + c0;
                    atomicAdd(dst + 0, racc[0]);
                    atomicAdd(dst + 1, racc[1]);
                    atomicAdd(dst + 2, racc[2]);
                    atomicAdd(dst + 3, racc[3]);
                }
                cur_i = i;
                racc[0] = v0; racc[1] = v1; racc[2] = v2; racc[3] = v3;
            } else {
                racc[0] += v0; racc[1] += v1; racc[2] += v2; racc[3] += v3;
            }
        }
    }
    if (cur_i >= 0) {
        float* dst = mout + (size_t)cur_i * 128 + c0;
        atomicAdd(dst + 0, racc[0]);
        atomicAdd(dst + 1, racc[1]);
        atomicAdd(dst + 2, racc[2]);
        atomicAdd(dst + 3, racc[3]);
    }
}

// ---------------------------------------------------------------------------
// Launch
// ---------------------------------------------------------------------------
extern "C" void kernel_launch(void* const* d_in, const int* in_sizes, int n_in,
                              void* d_out, int out_size) {
    const float* x    = (const float*)d_in[0];
    const float* rbf  = (const float*)d_in[1];
    const float* Wk2f = (const float*)d_in[2];
    const float* Wi   = (const float*)d_in[3];
    const float* bi   = (const float*)d_in[4];
    const float* Wj   = (const float*)d_in[5];
    const float* bj   = (const float*)d_in[6];
    const float* Wr1  = (const float*)d_in[7];
    const float* br1  = (const float*)d_in[8];
    const float* Wr2  = (const float*)d_in[9];
    const float* br2  = (const float*)d_in[10];
    const float* Wf   = (const float*)d_in[11];
    const float* bfb  = (const float*)d_in[12];
    const float* u    = (const float*)d_in[13];
    const int* idx_i  = (const int*)d_in[14];
    const int* idx_j  = (const int*)d_in[15];
    float* out = (float*)d_out;

    void *p_xa, *p_m, *p_xjall, *p_y, *p_wt2, *p_wk;
    cudaGetSymbolAddress(&p_xa, g_xa);
    cudaGetSymbolAddress(&p_m, g_m);
    cudaGetSymbolAddress(&p_xjall, g_xjall);
    cudaGetSymbolAddress(&p_y, g_y);
    cudaGetSymbolAddress(&p_wt2, g_wt2);
    cudaGetSymbolAddress(&p_wk, g_wk2f2);
    float* xa = (float*)p_xa;
    float* m = (float*)p_m;
    float* xjall = (float*)p_xjall;
    float* y = (float*)p_y;
    u64* wt2 = (u64*)p_wt2;
    u64* wk2f2 = (u64*)p_wk;

    const int SMEM_GEMM = 65536 + 32768;   // 96KB
    const int SMEM_EDGE = 32768 + 16384;   // 48KB
    cudaFuncSetAttribute(gemm128_f2<false, true, 0>,
                         cudaFuncAttributeMaxDynamicSharedMemorySize, SMEM_GEMM);
    cudaFuncSetAttribute(gemm128_f2<true, true, 0>,
                         cudaFuncAttributeMaxDynamicSharedMemorySize, SMEM_GEMM);
    cudaFuncSetAttribute(gemm128_f2<false, false, 1>,
                         cudaFuncAttributeMaxDynamicSharedMemorySize, SMEM_GEMM);
    cudaFuncSetAttribute(gemm128_f2<true, false, 2>,
                         cudaFuncAttributeMaxDynamicSharedMemorySize, SMEM_GEMM);
    cudaFuncSetAttribute(edge_f2,
                         cudaFuncAttributeMaxDynamicSharedMemorySize, SMEM_EDGE);

    // pack weights (pair-transposed)
    pack_kernel<<<32, 256>>>(Wi, wt2 + 0 * 8192, 64);
    pack_kernel<<<32, 256>>>(Wj, wt2 + 1 * 8192, 64);
    for (int l = 0; l < L_; ++l) {
        pack_kernel<<<32, 256>>>(Wr1 + (size_t)l * F_ * F_, wt2 + (2 + l) * 8192, 64);
        pack_kernel<<<32, 256>>>(Wr2 + (size_t)l * F_ * F_, wt2 + (5 + l) * 8192, 64);
    }
    pack_kernel<<<32, 256>>>(Wf, wt2 + 8 * 8192, 64);
    pack_kernel<<<16, 256>>>(Wk2f, wk2f2, 32);

    int ew_blocks = (N_ * F_ / 4 + 255) / 256;
    int gemm_blocks = (N_ + 63) / 64;
    int edge_blocks = (E_ + 511) / 512;

    // xa = ssp(x)
    prep_kernel<<<ew_blocks, 256>>>(x, xa);
    // m = xi = ssp(xa @ Wi + bi)
    gemm128_f2<false, true, 0><<<gemm_blocks, 256, SMEM_GEMM>>>(
        xa, wt2 + 0 * 8192, bi, m, nullptr, nullptr, N_);
    // xjall = ssp(xa @ Wj + bj)
    gemm128_f2<false, true, 0><<<gemm_blocks, 256, SMEM_GEMM>>>(
        xa, wt2 + 1 * 8192, bj, xjall, nullptr, nullptr, N_);
    // m += segment_sum(g * xjall[idx_j], idx_i)   (adds directly into xi)
    edge_f2<<<edge_blocks, 256, SMEM_EDGE>>>(rbf, wk2f2, xjall, idx_i, idx_j, m);

    // residual blocks
    for (int l = 0; l < L_; ++l) {
        gemm128_f2<true, true, 0><<<gemm_blocks, 256, SMEM_GEMM>>>(
            m, wt2 + (2 + l) * 8192, br1 + (size_t)l * F_, y, nullptr, nullptr, N_);
        gemm128_f2<false, false, 1><<<gemm_blocks, 256, SMEM_GEMM>>>(
            y, wt2 + (5 + l) * 8192, br2 + (size_t)l * F_, m, nullptr, nullptr, N_);
    }

    // out = u * x + ssp(m) @ Wf + bf
    gemm128_f2<true, false, 2><<<gemm_blocks, 256, SMEM_GEMM>>>(
        m, wt2 + 8 * 8192, bfb, out, x, u, N_);
}

// round 4
// speedup vs baseline: 2.2825x; 1.0623x over previous
#include <cuda_runtime.h>
#include <cstdint>

#define N_ 50000
#define F_ 128
#define E_ 800000
#define K_ 64
#define L_ 3

using u64 = unsigned long long;

// Scratch (static device globals — no runtime allocation)
__device__ float g_xa[(size_t)N_ * F_];     // ssp(x)
__device__ float g_m[(size_t)N_ * F_];      // xi, then m (edge kernel adds into it)
__device__ float g_xjall[(size_t)N_ * F_];  // ssp(xa@Wj+bj)
__device__ float g_y[(size_t)N_ * F_];      // residual temp
__device__ u64 g_wk2f2[32 * 128];           // k-split packed Wk2f (edge kernel)

__device__ __forceinline__ float ssp(float v) {
    float ax = fabsf(v);
    float sp = fmaxf(v, 0.0f) + log1pf(__expf(-ax));
    return sp - 0.69314718055994530942f;
}
__device__ __forceinline__ float4 ssp4(float4 v) {
    v.x = ssp(v.x); v.y = ssp(v.y); v.z = ssp(v.z); v.w = ssp(v.w);
    return v;
}

// packed f32x2 FMA: d = a*b + c (lane-wise on the two fp32 halves)
__device__ __forceinline__ u64 ffma2(u64 a, u64 b, u64 c) {
    u64 d;
    asm("fma.rn.f32x2 %0, %1, %2, %3;" : "=l"(d) : "l"(a), "l"(b), "l"(c));
    return d;
}
// replicate one fp32 into both f32x2 lanes
__device__ __forceinline__ u64 rep2(float a) {
    u64 d;
    unsigned r = __float_as_uint(a);
    asm("mov.b64 %0, {%1, %1};" : "=l"(d) : "r"(r));
    return d;
}
__device__ __forceinline__ float lo32(u64 v) { return __uint_as_float((unsigned)v); }
__device__ __forceinline__ float hi32(u64 v) { return __uint_as_float((unsigned)(v >> 32)); }
__device__ __forceinline__ float pairsum(u64 v) { return lo32(v) + hi32(v); }

// ---------------------------------------------------------------------------
// Pack Wk2f (k-split pairs for the edge kernel):
// out[k2*128 + c] = (W[2k2][c], W[2k2+1][c]),  halfK = 32
// ---------------------------------------------------------------------------
__global__ void pack_kernel(const float* __restrict__ W, u64* __restrict__ out,
                            int halfK) {
    int i = blockIdx.x * blockDim.x + threadIdx.x;
    if (i < halfK * 128) {
        int k2 = i >> 7, c = i & 127;
        unsigned lo = __float_as_uint(W[(2 * k2) * 128 + c]);
        unsigned hi = __float_as_uint(W[(2 * k2 + 1) * 128 + c]);
        out[i] = ((u64)hi << 32) | lo;
    }
}

// xa = ssp(x)
__global__ void prep_kernel(const float* __restrict__ x, float* __restrict__ xa) {
    int i = blockIdx.x * blockDim.x + threadIdx.x;
    if (i < N_ * F_ / 4) {
        float4 v = reinterpret_cast<const float4*>(x)[i];
        reinterpret_cast<float4*>(xa)[i] = ssp4(v);
    }
}

// ---------------------------------------------------------------------------
// Node GEMM (broadcast-A, column-pair f32x2): C = ep([ssp?](A) @ W + bias).
// W is plain row-major [K=128][C=128]; (c,c+1) pairs read as native u64.
// Block = 64 rows x 128 cols, 256 threads. Warp = 8 rows x 128 cols;
// thread = 8 rows x 4 cols (2 f32x2 col-pair accumulators per row).
// A loads are warp-uniform float4 broadcasts (1 crossbar phase each).
// EP: 0 -> r, 1 -> C+r, 2 -> u*x + r
// ---------------------------------------------------------------------------
template <bool IN_ACT, bool OUT_ACT, int EP>
__global__ __launch_bounds__(256, 2)
void gemm128_cp(const float* __restrict__ A, const float* __restrict__ W,
                const float* __restrict__ bias, float* __restrict__ C,
                const float* __restrict__ x, const float* __restrict__ u,
                int n) {
    extern __shared__ __align__(16) char smraw[];
    float* Ws = reinterpret_cast<float*>(smraw);           // [128 k][128 c] 64KB
    float* As = reinterpret_cast<float*>(smraw + 65536);   // [64 r][128 k] 32KB

    int tid = threadIdx.x;
    int row0 = blockIdx.x * 64;

    // stage W (plain copy): 4096 float4
    {
        const float4* W4 = reinterpret_cast<const float4*>(W);
        float4* Ws4 = reinterpret_cast<float4*>(Ws);
#pragma unroll
        for (int i = 0; i < 16; ++i) Ws4[tid + i * 256] = W4[tid + i * 256];
    }
    // stage A tile (guarded, optional ssp)
    {
        const float4* A4 = reinterpret_cast<const float4*>(A);
        float4* As4 = reinterpret_cast<float4*>(As);
#pragma unroll
        for (int i = 0; i < 8; ++i) {
            int idx = tid + i * 256;       // 0..2047
            int r = idx >> 5;
            int k4 = idx & 31;
            float4 v = make_float4(0.f, 0.f, 0.f, 0.f);
            if (row0 + r < n) v = A4[(size_t)(row0 + r) * 32 + k4];
            if (IN_ACT) v = ssp4(v);
            As4[idx] = v;
        }
    }
    __syncthreads();

    int l = tid & 31;        // lane: cols 4l..4l+3
    int w = tid >> 5;        // warp: rows w*8..w*8+7
    int r0 = w * 8;

    u64 acc[8][2];
#pragma unroll
    for (int i = 0; i < 8; ++i) { acc[i][0] = 0ull; acc[i][1] = 0ull; }

    const float4* As4c = reinterpret_cast<const float4*>(As);
    const ulonglong2* Ws2 = reinterpret_cast<const ulonglong2*>(Ws);

#pragma unroll 2
    for (int kc = 0; kc < 32; ++kc) {     // 4 k per iter
        ulonglong2 wk0 = Ws2[(4 * kc + 0) * 32 + l];
        ulonglong2 wk1 = Ws2[(4 * kc + 1) * 32 + l];
        ulonglong2 wk2 = Ws2[(4 * kc + 2) * 32 + l];
        ulonglong2 wk3 = Ws2[(4 * kc + 3) * 32 + l];
#pragma unroll
        for (int i = 0; i < 8; ++i) {
            float4 a = As4c[(r0 + i) * 32 + kc];   // warp-uniform broadcast
            u64 aa;
            aa = rep2(a.x);
            acc[i][0] = ffma2(aa, wk0.x, acc[i][0]);
            acc[i][1] = ffma2(aa, wk0.y, acc[i][1]);
            aa = rep2(a.y);
            acc[i][0] = ffma2(aa, wk1.x, acc[i][0]);
            acc[i][1] = ffma2(aa, wk1.y, acc[i][1]);
            aa = rep2(a.z);
            acc[i][0] = ffma2(aa, wk2.x, acc[i][0]);
            acc[i][1] = ffma2(aa, wk2.y, acc[i][1]);
            aa = rep2(a.w);
            acc[i][0] = ffma2(aa, wk3.x, acc[i][0]);
            acc[i][1] = ffma2(aa, wk3.y, acc[i][1]);
        }
    }

    float4 b4 = reinterpret_cast<const float4*>(bias)[l];
    float4* C4 = reinterpret_cast<float4*>(C);

#pragma unroll
    for (int i = 0; i < 8; ++i) {
        int r = row0 + r0 + i;
        if (r >= n) break;
        float4 v;
        v.x = lo32(acc[i][0]) + b4.x;
        v.y = hi32(acc[i][0]) + b4.y;
        v.z = lo32(acc[i][1]) + b4.z;
        v.w = hi32(acc[i][1]) + b4.w;
        if constexpr (EP == 1) {
            float4 old = C4[(size_t)r * 32 + l];
            v.x += old.x; v.y += old.y; v.z += old.z; v.w += old.w;
        }
        if constexpr (EP == 2) {
            float4 xv = reinterpret_cast<const float4*>(x)[(size_t)r * 32 + l];
            float4 u4 = reinterpret_cast<const float4*>(u)[l];
            v.x += u4.x * xv.x; v.y += u4.y * xv.y;
            v.z += u4.z * xv.z; v.w += u4.w * xv.w;
        }
        if constexpr (OUT_ACT) v = ssp4(v);
        C4[(size_t)r * 32 + l] = v;
    }
}

// ---------------------------------------------------------------------------
// Edge kernel (f32x2, k-split, register-blocked over edges):
//   g = rbf[e,:] @ Wk2f ; msg = g * xjall[idx_j[e]] ; m[idx_i[e]] += msg
// Block: 512 edges (8 tiles of 64). 256 threads = 8 warps (8 edges each)
// x 32 col-groups (4 cols each). K=64 -> 16 k-iterations.
// rbf loads are warp-broadcasts; sorted idx_i -> run-length accumulate.
// ---------------------------------------------------------------------------
__global__ __launch_bounds__(256, 2)
void edge_f2(const float* __restrict__ rbf, const u64* __restrict__ Wt2,
             const float* __restrict__ xjall, const int* __restrict__ ii,
             const int* __restrict__ jj, float* __restrict__ mout) {
    extern __shared__ __align__(16) char smraw[];
    u64* Ws = reinterpret_cast<u64*>(smraw);             // [32 k2][128 c] = 32KB
    float* rs = reinterpret_cast<float*>(smraw + 32768);   // [64 e][64 k] = 16KB

    int tid = threadIdx.x;

    // stage packed Wk2f: 4096 u64 = 2048 ulonglong2
    {
        const ulonglong2* src = reinterpret_cast<const ulonglong2*>(Wt2);
        ulonglong2* dst = reinterpret_cast<ulonglong2*>(Ws);
#pragma unroll
        for (int i = 0; i < 8; ++i) dst[tid + i * 256] = src[tid + i * 256];
    }

    int tx = tid & 31;     // col group: cols tx*4..tx*4+3
    int eg = tid >> 5;     // warp id = edge group (8 contiguous edges)
    int c0 = tx * 4;
    long base = (long)blockIdx.x * 512;

    const float4* rbf4 = reinterpret_cast<const float4*>(rbf);
    float4* rs4 = reinterpret_cast<float4*>(rs);
    const ulonglong2* rs2 = reinterpret_cast<const ulonglong2*>(rs);
    const ulonglong2* Ws2 = reinterpret_cast<const ulonglong2*>(Ws);

    int cur_i = -1;
    float racc[4] = {0.f, 0.f, 0.f, 0.f};

    for (int t = 0; t < 8; ++t) {
        __syncthreads();
        // stage rbf for 64 edges: 1024 float4
#pragma unroll
        for (int s = 0; s < 4; ++s) {
            int idx = tid + s * 256;     // 0..1023
            int er = idx >> 4;           // local edge 0..63
            int k4 = idx & 15;
            long e = base + t * 64 + er;
            float4 v = make_float4(0.f, 0.f, 0.f, 0.f);
            if (e < E_) v = rbf4[e * 16 + k4];
            rs4[er * 16 + k4] = v;
        }
        __syncthreads();

        u64 acc[8][4];
#pragma unroll
        for (int el = 0; el < 8; ++el)
#pragma unroll
            for (int j = 0; j < 4; ++j) acc[el][j] = 0ull;

#pragma unroll 2
        for (int kk = 0; kk < 16; ++kk) {   // 4 k per iter x 16 = K=64
            ulonglong2 wa0 = Ws2[(2 * kk) * 64 + tx * 2];
            ulonglong2 wa1 = Ws2[(2 * kk) * 64 + tx * 2 + 1];
            ulonglong2 wb0 = Ws2[(2 * kk + 1) * 64 + tx * 2];
            ulonglong2 wb1 = Ws2[(2 * kk + 1) * 64 + tx * 2 + 1];
#pragma unroll
            for (int el = 0; el < 8; ++el) {
                ulonglong2 a = rs2[(eg * 8 + el) * 16 + kk];  // broadcast
                acc[el][0] = ffma2(a.x, wa0.x, acc[el][0]);
                acc[el][1] = ffma2(a.x, wa0.y, acc[el][1]);
                acc[el][2] = ffma2(a.x, wa1.x, acc[el][2]);
                acc[el][3] = ffma2(a.x, wa1.y, acc[el][3]);
                acc[el][0] = ffma2(a.y, wb0.x, acc[el][0]);
                acc[el][1] = ffma2(a.y, wb0.y, acc[el][1]);
                acc[el][2] = ffma2(a.y, wb1.x, acc[el][2]);
                acc[el][3] = ffma2(a.y, wb1.y, acc[el][3]);
            }
        }

        // epilogue: gather + gate + run-length scatter (idx_i sorted)
#pragma unroll
        for (int el = 0; el < 8; ++el) {
            long e = base + t * 64 + eg * 8 + el;
            if (e >= E_) break;
            int i = __ldg(ii + e);
            int j = __ldg(jj + e);
            float4 xv = __ldg(reinterpret_cast<const float4*>(
                                  xjall + (size_t)j * 128) + tx);
            float v0 = pairsum(acc[el][0]) * xv.x;
            float v1 = pairsum(acc[el][1]) * xv.y;
            float v2 = pairsum(acc[el][2]) * xv.z;
            float v3 = pairsum(acc[el][3]) * xv.w;
            if (i != cur_i) {
                if (cur_i >= 0) {
                    float* dst = mout + (size_t)cur_i * 128 + c0;
                    atomicAdd(dst + 0, racc[0]);
                    atomicAdd(dst + 1, racc[1]);
                    atomicAdd(dst + 2, racc[2]);
                    atomicAdd(dst + 3, racc[3]);
                }
                cur_i = i;
                racc[0] = v0; racc[1] = v1; racc[2] = v2; racc[3] = v3;
            } else {
                racc[0] += v0; racc[1] += v1; racc[2] += v2; racc[3] += v3;
            }
        }
    }
    if (cur_i >= 0) {
        float* dst = mout + (size_t)cur_i * 128 + c0;
        atomicAdd(dst + 0, racc[0]);
        atomicAdd(dst + 1, racc[1]);
        atomicAdd(dst + 2, racc[2]);
        atomicAdd(dst + 3, racc[3]);
    }
}

// ---------------------------------------------------------------------------
// Launch
// ---------------------------------------------------------------------------
extern "C" void kernel_launch(void* const* d_in, const int* in_sizes, int n_in,
                              void* d_out, int out_size) {
    const float* x    = (const float*)d_in[0];
    const float* rbf  = (const float*)d_in[1];
    const float* Wk2f = (const float*)d_in[2];
    const float* Wi   = (const float*)d_in[3];
    const float* bi   = (const float*)d_in[4];
    const float* Wj   = (const float*)d_in[5];
    const float* bj   = (const float*)d_in[6];
    const float* Wr1  = (const float*)d_in[7];
    const float* br1  = (const float*)d_in[8];
    const float* Wr2  = (const float*)d_in[9];
    const float* br2  = (const float*)d_in[10];
    const float* Wf   = (const float*)d_in[11];
    const float* bfb  = (const float*)d_in[12];
    const float* u    = (const float*)d_in[13];
    const int* idx_i  = (const int*)d_in[14];
    const int* idx_j  = (const int*)d_in[15];
    float* out = (float*)d_out;

    void *p_xa, *p_m, *p_xjall, *p_y, *p_wk;
    cudaGetSymbolAddress(&p_xa, g_xa);
    cudaGetSymbolAddress(&p_m, g_m);
    cudaGetSymbolAddress(&p_xjall, g_xjall);
    cudaGetSymbolAddress(&p_y, g_y);
    cudaGetSymbolAddress(&p_wk, g_wk2f2);
    float* xa = (float*)p_xa;
    float* m = (float*)p_m;
    float* xjall = (float*)p_xjall;
    float* y = (float*)p_y;
    u64* wk2f2 = (u64*)p_wk;

    const int SMEM_GEMM = 65536 + 32768;   // 96KB
    const int SMEM_EDGE = 32768 + 16384;   // 48KB
    cudaFuncSetAttribute(gemm128_cp<false, true, 0>,
                         cudaFuncAttributeMaxDynamicSharedMemorySize, SMEM_GEMM);
    cudaFuncSetAttribute(gemm128_cp<true, true, 0>,
                         cudaFuncAttributeMaxDynamicSharedMemorySize, SMEM_GEMM);
    cudaFuncSetAttribute(gemm128_cp<false, false, 1>,
                         cudaFuncAttributeMaxDynamicSharedMemorySize, SMEM_GEMM);
    cudaFuncSetAttribute(gemm128_cp<true, false, 2>,
                         cudaFuncAttributeMaxDynamicSharedMemorySize, SMEM_GEMM);
    cudaFuncSetAttribute(edge_f2,
                         cudaFuncAttributeMaxDynamicSharedMemorySize, SMEM_EDGE);

    // pack only Wk2f (k-split for edge kernel)
    pack_kernel<<<16, 256>>>(Wk2f, wk2f2, 32);

    int ew_blocks = (N_ * F_ / 4 + 255) / 256;
    int gemm_blocks = (N_ + 63) / 64;
    int edge_blocks = (E_ + 511) / 512;

    // xa = ssp(x)
    prep_kernel<<<ew_blocks, 256>>>(x, xa);
    // m = xi = ssp(xa @ Wi + bi)
    gemm128_cp<false, true, 0><<<gemm_blocks, 256, SMEM_GEMM>>>(
        xa, Wi, bi, m, nullptr, nullptr, N_);
    // xjall = ssp(xa @ Wj + bj)
    gemm128_cp<false, true, 0><<<gemm_blocks, 256, SMEM_GEMM>>>(
        xa, Wj, bj, xjall, nullptr, nullptr, N_);
    // m += segment_sum(g * xjall[idx_j], idx_i)   (adds directly into xi)
    edge_f2<<<edge_blocks, 256, SMEM_EDGE>>>(rbf, wk2f2, xjall, idx_i, idx_j, m);

    // residual blocks
    for (int l = 0; l < L_; ++l) {
        gemm128_cp<true, true, 0><<<gemm_blocks, 256, SMEM_GEMM>>>(
            m, Wr1 + (size_t)l * F_ * F_, br1 + (size_t)l * F_, y,
            nullptr, nullptr, N_);
        gemm128_cp<false, false, 1><<<gemm_blocks, 256, SMEM_GEMM>>>(
            y, Wr2 + (size_t)l * F_ * F_, br2 + (size_t)l * F_, m,
            nullptr, nullptr, N_);
    }

    // out = u * x + ssp(m) @ Wf + bf
    gemm128_cp<true, false, 2><<<gemm_blocks, 256, SMEM_GEMM>>>(
        m, Wf, bfb, out, x, u, N_);
}

// round 6
// speedup vs baseline: 2.4577x; 1.0768x over previous
#include <cuda_runtime.h>
#include <cuda_bf16.h>
#include <cstdint>

#define N_ 50000
#define F_ 128
#define E_ 800000
#define K_ 64
#define L_ 3

using u64 = unsigned long long;

// ---------------------------------------------------------------------------
// Scratch (static device globals — no runtime allocation)
// ---------------------------------------------------------------------------
__device__ float g_m[(size_t)N_ * F_];      // xi, then m (edge kernel adds into it)
__device__ float g_xjall[(size_t)N_ * F_];  // ssp(xa@Wj+bj)
__device__ float g_y[(size_t)N_ * F_];      // residual temp
__device__ u64 g_wk2f2[32 * 128];           // k-split packed Wk2f (edge kernel)
// bf16-split transposed node weights: [mat 0..8][c 0..127][k 0..127]
__device__ __nv_bfloat16 g_wthi[9 * 128 * 128];
__device__ __nv_bfloat16 g_wtlo[9 * 128 * 128];

__device__ __forceinline__ float ssp(float v) {
    float ax = fabsf(v);
    float sp = fmaxf(v, 0.0f) + log1pf(__expf(-ax));
    return sp - 0.69314718055994530942f;
}
__device__ __forceinline__ float4 ssp4(float4 v) {
    v.x = ssp(v.x); v.y = ssp(v.y); v.z = ssp(v.z); v.w = ssp(v.w);
    return v;
}

__device__ __forceinline__ u64 ffma2(u64 a, u64 b, u64 c) {
    u64 d;
    asm("fma.rn.f32x2 %0, %1, %2, %3;" : "=l"(d) : "l"(a), "l"(b), "l"(c));
    return d;
}
__device__ __forceinline__ float lo32(u64 v) { return __uint_as_float((unsigned)v); }
__device__ __forceinline__ float hi32(u64 v) { return __uint_as_float((unsigned)(v >> 32)); }
__device__ __forceinline__ float pairsum(u64 v) { return lo32(v) + hi32(v); }

__device__ __forceinline__ uint32_t smem_u32(const void* p) {
    uint32_t a;
    asm("{ .reg .u64 t; cvta.to.shared.u64 t, %1; cvt.u32.u64 %0, t; }"
        : "=r"(a) : "l"(p));
    return a;
}

// ldmatrix x4 (non-transposed), b16
__device__ __forceinline__ void ldsm4(unsigned* r, uint32_t addr) {
    asm volatile(
        "ldmatrix.sync.aligned.m8n8.x4.shared.b16 {%0,%1,%2,%3}, [%4];"
        : "=r"(r[0]), "=r"(r[1]), "=r"(r[2]), "=r"(r[3]) : "r"(addr));
}

// mma m16n8k16 bf16 -> f32, accumulate in place
__device__ __forceinline__ void mma16816(float* d, const unsigned* a,
                                         const unsigned b0, const unsigned b1) {
    asm volatile(
        "mma.sync.aligned.m16n8k16.row.col.f32.bf16.bf16.f32 "
        "{%0,%1,%2,%3}, {%4,%5,%6,%7}, {%8,%9}, {%0,%1,%2,%3};"
        : "+f"(d[0]), "+f"(d[1]), "+f"(d[2]), "+f"(d[3])
        : "r"(a[0]), "r"(a[1]), "r"(a[2]), "r"(a[3]), "r"(b0), "r"(b1));
}

// ---------------------------------------------------------------------------
// Pack node weights: W[k][c] fp32 -> WT_hi/lo[c][k] bf16 (one launch, 9 mats)
// ---------------------------------------------------------------------------
__global__ void packw_kernel(const float* __restrict__ Wi,
                             const float* __restrict__ Wj,
                             const float* __restrict__ Wr1,
                             const float* __restrict__ Wr2,
                             const float* __restrict__ Wf,
                             __nv_bfloat16* __restrict__ hi,
                             __nv_bfloat16* __restrict__ lo) {
    int m = blockIdx.y;
    const float* W;
    if (m == 0) W = Wi;
    else if (m == 1) W = Wj;
    else if (m < 5) W = Wr1 + (size_t)(m - 2) * F_ * F_;
    else if (m < 8) W = Wr2 + (size_t)(m - 5) * F_ * F_;
    else W = Wf;
    int i = blockIdx.x * blockDim.x + threadIdx.x;
    if (i < 128 * 128) {
        int c = i >> 7, k = i & 127;
        float f = W[k * 128 + c];
        __nv_bfloat16 h = __float2bfloat16_rn(f);
        __nv_bfloat16 l = __float2bfloat16_rn(f - __bfloat162float(h));
        hi[(size_t)m * 16384 + i] = h;
        lo[(size_t)m * 16384 + i] = l;
    }
}

// pack Wk2f (k-split pairs for the edge kernel)
__global__ void pack_kernel(const float* __restrict__ W, u64* __restrict__ out,
                            int halfK) {
    int i = blockIdx.x * blockDim.x + threadIdx.x;
    if (i < halfK * 128) {
        int k2 = i >> 7, c = i & 127;
        unsigned lo = __float_as_uint(W[(2 * k2) * 128 + c]);
        unsigned hi = __float_as_uint(W[(2 * k2 + 1) * 128 + c]);
        out[i] = ((u64)hi << 32) | lo;
    }
}

// ---------------------------------------------------------------------------
// mma.sync node GEMM: C = ep( [ssp?](A) @ W + bias ), 128x128x128 tiles.
// 2-term bf16 split: D = Ahi*Whi + Ahi*Wlo + Alo*Whi (fp32 accum).
// 256 threads / 8 warps: warp = 32 rows x 64 cols (2 m16 x 8 n8 tiles).
// Smem tiles padded to 136 bf16 per row (conflict-free ldmatrix).
// EP: 0 -> r, 1 -> C+r, 2 -> u*x + r
// ---------------------------------------------------------------------------
#define LDA 136
#define PLANE (128 * LDA * 2)     // 34816 B per bf16 plane
#define SM_AHI 0
#define SM_ALO (SM_AHI + PLANE)
#define SM_WHI (SM_ALO + PLANE)
#define SM_WLO (SM_WHI + PLANE)
#define SM_TOTAL (SM_WLO + PLANE)

template <bool IN_ACT, bool OUT_ACT, int EP>
__global__ __launch_bounds__(256, 1)
void gemm_mma(const float* __restrict__ A,
              const __nv_bfloat16* __restrict__ wthi,
              const __nv_bfloat16* __restrict__ wtlo,
              const float* __restrict__ bias, float* __restrict__ C,
              const float* __restrict__ x, const float* __restrict__ u,
              int n) {
    extern __shared__ __align__(16) char sm[];
    uint32_t smb = smem_u32(sm);
    int tid = threadIdx.x;
    int wid = tid >> 5;
    int lane = tid & 31;
    int row0 = blockIdx.x * 128;

    // stage W hi/lo: [c][k] row-major -> [128][LDA] padded
    {
        const uint4* srcH = reinterpret_cast<const uint4*>(wthi);
        const uint4* srcL = reinterpret_cast<const uint4*>(wtlo);
#pragma unroll
        for (int it = 0; it < 8; ++it) {
            int idx = tid + it * 256;      // 0..2047
            int row = idx >> 4;
            int seg = idx & 15;
            uint32_t off = (uint32_t)(row * LDA + seg * 8) * 2;
            *reinterpret_cast<uint4*>(sm + SM_WHI + off) = srcH[idx];
            *reinterpret_cast<uint4*>(sm + SM_WLO + off) = srcL[idx];
        }
    }
    // stage A hi/lo: fp32 -> ssp? -> bf16 split
    {
        const float4* A4 = reinterpret_cast<const float4*>(A);
#pragma unroll
        for (int it = 0; it < 16; ++it) {
            int idx = tid + it * 256;      // 0..4095
            int row = idx >> 5;
            int k4 = idx & 31;
            float4 v = make_float4(0.f, 0.f, 0.f, 0.f);
            if (row0 + row < n) v = A4[(size_t)(row0 + row) * 32 + k4];
            if (IN_ACT) v = ssp4(v);
            __nv_bfloat162 h01 = __floats2bfloat162_rn(v.x, v.y);
            __nv_bfloat162 h23 = __floats2bfloat162_rn(v.z, v.w);
            __nv_bfloat162 l01 = __floats2bfloat162_rn(
                v.x - __bfloat162float(h01.x), v.y - __bfloat162float(h01.y));
            __nv_bfloat162 l23 = __floats2bfloat162_rn(
                v.z - __bfloat162float(h23.x), v.w - __bfloat162float(h23.y));
            uint32_t off = (uint32_t)(row * LDA + k4 * 4) * 2;
            u64 hv = ((u64)*reinterpret_cast<uint32_t*>(&h23) << 32) |
                     *reinterpret_cast<uint32_t*>(&h01);
            u64 lv = ((u64)*reinterpret_cast<uint32_t*>(&l23) << 32) |
                     *reinterpret_cast<uint32_t*>(&l01);
            *reinterpret_cast<u64*>(sm + SM_AHI + off) = hv;
            *reinterpret_cast<u64*>(sm + SM_ALO + off) = lv;
        }
    }
    __syncthreads();

    int warp_m = wid & 3;        // 4 row groups x 32 rows
    int warp_n = wid >> 2;       // 2 col groups x 64 cols

    float d[2][8][4];
#pragma unroll
    for (int mt = 0; mt < 2; ++mt)
#pragma unroll
        for (int nt = 0; nt < 8; ++nt)
#pragma unroll
            for (int q = 0; q < 4; ++q) d[mt][nt][q] = 0.f;

    // per-lane ldmatrix base offsets (element units)
    // A tile (m16): lanes 0-7 rows0-7/k0-7, 8-15 rows8-15/k0-7,
    //               16-23 rows0-7/k8-15, 24-31 rows8-15/k8-15
    int a_row = warp_m * 32 + (lane & 15);
    int a_k8 = (lane >> 4) * 8;
    // B pair-tile (two n8): lanes 0-7 n0-7/k0-7, 8-15 n0-7/k8-15,
    //                       16-23 n8-15/k0-7, 24-31 n8-15/k8-15
    int b_n = warp_n * 64 + (lane >> 4) * 8 + (lane & 7);
    int b_k8 = ((lane >> 3) & 1) * 8;

#pragma unroll
    for (int ks = 0; ks < 8; ++ks) {
        int kb = ks * 16;
        unsigned bh[4][4], bl[4][4], ah[2][4], al[2][4];
#pragma unroll
        for (int p = 0; p < 4; ++p) {
            uint32_t boff =
                (uint32_t)((b_n + p * 16) * LDA + kb + b_k8) * 2;
            ldsm4(bh[p], smb + SM_WHI + boff);
            ldsm4(bl[p], smb + SM_WLO + boff);
        }
#pragma unroll
        for (int mt = 0; mt < 2; ++mt) {
            uint32_t aoff =
                (uint32_t)((a_row + mt * 16) * LDA + kb + a_k8) * 2;
            ldsm4(ah[mt], smb + SM_AHI + aoff);
            ldsm4(al[mt], smb + SM_ALO + aoff);
        }
#pragma unroll
        for (int mt = 0; mt < 2; ++mt) {
#pragma unroll
            for (int nt = 0; nt < 8; ++nt) {
                unsigned bh0 = bh[nt >> 1][(nt & 1) * 2];
                unsigned bh1 = bh[nt >> 1][(nt & 1) * 2 + 1];
                unsigned bl0 = bl[nt >> 1][(nt & 1) * 2];
                unsigned bl1 = bl[nt >> 1][(nt & 1) * 2 + 1];
                mma16816(d[mt][nt], ah[mt], bh0, bh1);
                mma16816(d[mt][nt], ah[mt], bl0, bl1);
                mma16816(d[mt][nt], al[mt], bh0, bh1);
            }
        }
    }

    // epilogue: d0,d1 -> (r, c), d2,d3 -> (r+8, c); c = 2*(lane%4) in n8 tile
    const float2* bias2 = reinterpret_cast<const float2*>(bias);
    float2* C2 = reinterpret_cast<float2*>(C);
    const float2* x2 = reinterpret_cast<const float2*>(x);
    const float2* u2 = reinterpret_cast<const float2*>(u);

#pragma unroll
    for (int mt = 0; mt < 2; ++mt) {
#pragma unroll
        for (int half = 0; half < 2; ++half) {
            int r = row0 + warp_m * 32 + mt * 16 + (lane >> 2) + half * 8;
            if (r >= n) continue;
#pragma unroll
            for (int nt = 0; nt < 8; ++nt) {
                int c = warp_n * 64 + nt * 8 + (lane & 3) * 2;
                int ci = c >> 1;
                float2 bb = bias2[ci];
                float2 v;
                v.x = d[mt][nt][half * 2 + 0] + bb.x;
                v.y = d[mt][nt][half * 2 + 1] + bb.y;
                size_t gi = (size_t)r * 64 + ci;
                if constexpr (EP == 1) {
                    float2 o = C2[gi];
                    v.x += o.x; v.y += o.y;
                }
                if constexpr (EP == 2) {
                    float2 xv = x2[gi];
                    float2 uv = u2[ci];
                    v.x += uv.x * xv.x; v.y += uv.y * xv.y;
                }
                if constexpr (OUT_ACT) { v.x = ssp(v.x); v.y = ssp(v.y); }
                C2[gi] = v;
            }
        }
    }
}

// ---------------------------------------------------------------------------
// Edge kernel (f32x2, k-split, register-blocked over edges) — unchanged.
// ---------------------------------------------------------------------------
__global__ __launch_bounds__(256, 2)
void edge_f2(const float* __restrict__ rbf, const u64* __restrict__ Wt2,
             const float* __restrict__ xjall, const int* __restrict__ ii,
             const int* __restrict__ jj, float* __restrict__ mout) {
    extern __shared__ __align__(16) char smraw[];
    u64* Ws = reinterpret_cast<u64*>(smraw);               // 32KB
    float* rs = reinterpret_cast<float*>(smraw + 32768);   // 16KB

    int tid = threadIdx.x;
    {
        const ulonglong2* src = reinterpret_cast<const ulonglong2*>(Wt2);
        ulonglong2* dst = reinterpret_cast<ulonglong2*>(Ws);
#pragma unroll
        for (int i = 0; i < 8; ++i) dst[tid + i * 256] = src[tid + i * 256];
    }

    int tx = tid & 31;
    int eg = tid >> 5;
    int c0 = tx * 4;
    long base = (long)blockIdx.x * 512;

    const float4* rbf4 = reinterpret_cast<const float4*>(rbf);
    float4* rs4 = reinterpret_cast<float4*>(rs);
    const ulonglong2* rs2 = reinterpret_cast<const ulonglong2*>(rs);
    const ulonglong2* Ws2 = reinterpret_cast<const ulonglong2*>(Ws);

    int cur_i = -1;
    float racc[4] = {0.f, 0.f, 0.f, 0.f};

    for (int t = 0; t < 8; ++t) {
        __syncthreads();
#pragma unroll
        for (int s = 0; s < 4; ++s) {
            int idx = tid + s * 256;
            int er = idx >> 4;
            int k4 = idx & 15;
            long e = base + t * 64 + er;
            float4 v = make_float4(0.f, 0.f, 0.f, 0.f);
            if (e < E_) v = rbf4[e * 16 + k4];
            rs4[er * 16 + k4] = v;
        }
        __syncthreads();

        u64 acc[8][4];
#pragma unroll
        for (int el = 0; el < 8; ++el)
#pragma unroll
            for (int j = 0; j < 4; ++j) acc[el][j] = 0ull;

#pragma unroll 2
        for (int kk = 0; kk < 16; ++kk) {
            ulonglong2 wa0 = Ws2[(2 * kk) * 64 + tx * 2];
            ulonglong2 wa1 = Ws2[(2 * kk) * 64 + tx * 2 + 1];
            ulonglong2 wb0 = Ws2[(2 * kk + 1) * 64 + tx * 2];
            ulonglong2 wb1 = Ws2[(2 * kk + 1) * 64 + tx * 2 + 1];
#pragma unroll
            for (int el = 0; el < 8; ++el) {
                ulonglong2 a = rs2[(eg * 8 + el) * 16 + kk];
                acc[el][0] = ffma2(a.x, wa0.x, acc[el][0]);
                acc[el][1] = ffma2(a.x, wa0.y, acc[el][1]);
                acc[el][2] = ffma2(a.x, wa1.x, acc[el][2]);
                acc[el][3] = ffma2(a.x, wa1.y, acc[el][3]);
                acc[el][0] = ffma2(a.y, wb0.x, acc[el][0]);
                acc[el][1] = ffma2(a.y, wb0.y, acc[el][1]);
                acc[el][2] = ffma2(a.y, wb1.x, acc[el][2]);
                acc[el][3] = ffma2(a.y, wb1.y, acc[el][3]);
            }
        }

#pragma unroll
        for (int el = 0; el < 8; ++el) {
            long e = base + t * 64 + eg * 8 + el;
            if (e >= E_) break;
            int i = __ldg(ii + e);
            int j = __ldg(jj + e);
            float4 xv = __ldg(reinterpret_cast<const float4*>(
                                  xjall + (size_t)j * 128) + tx);
            float v0 = pairsum(acc[el][0]) * xv.x;
            float v1 = pairsum(acc[el][1]) * xv.y;
            float v2 = pairsum(acc[el][2]) * xv.z;
            float v3 = pairsum(acc[el][3]) * xv.w;
            if (i != cur_i) {
                if (cur_i >= 0) {
                    float* dst = mout + (size_t)cur_i * 128 + c0;
                    atomicAdd(dst + 0, racc[0]);
                    atomicAdd(dst + 1, racc[1]);
                    atomicAdd(dst + 2, racc[2]);
                    atomicAdd(dst + 3, racc[3]);
                }
                cur_i = i;
                racc[0] = v0; racc[1] = v1; racc[2] = v2; racc[3] = v3;
            } else {
                racc[0] += v0; racc[1] += v1; racc[2] += v2; racc[3] += v3;
            }
        }
    }
    if (cur_i >= 0) {
        float* dst = mout + (size_t)cur_i * 128 + c0;
        atomicAdd(dst + 0, racc[0]);
        atomicAdd(dst + 1, racc[1]);
        atomicAdd(dst + 2, racc[2]);
        atomicAdd(dst + 3, racc[3]);
    }
}

// ---------------------------------------------------------------------------
// Launch
// ---------------------------------------------------------------------------
extern "C" void kernel_launch(void* const* d_in, const int* in_sizes, int n_in,
                              void* d_out, int out_size) {
    const float* x    = (const float*)d_in[0];
    const float* rbf  = (const float*)d_in[1];
    const float* Wk2f = (const float*)d_in[2];
    const float* Wi   = (const float*)d_in[3];
    const float* bi   = (const float*)d_in[4];
    const float* Wj   = (const float*)d_in[5];
    const float* bj   = (const float*)d_in[6];
    const float* Wr1  = (const float*)d_in[7];
    const float* br1  = (const float*)d_in[8];
    const float* Wr2  = (const float*)d_in[9];
    const float* br2  = (const float*)d_in[10];
    const float* Wf   = (const float*)d_in[11];
    const float* bfb  = (const float*)d_in[12];
    const float* u    = (const float*)d_in[13];
    const int* idx_i  = (const int*)d_in[14];
    const int* idx_j  = (const int*)d_in[15];
    float* out = (float*)d_out;

    void *p_m, *p_xjall, *p_y, *p_wk, *p_hi, *p_lo;
    cudaGetSymbolAddress(&p_m, g_m);
    cudaGetSymbolAddress(&p_xjall, g_xjall);
    cudaGetSymbolAddress(&p_y, g_y);
    cudaGetSymbolAddress(&p_wk, g_wk2f2);
    cudaGetSymbolAddress(&p_hi, g_wthi);
    cudaGetSymbolAddress(&p_lo, g_wtlo);
    float* m = (float*)p_m;
    float* xjall = (float*)p_xjall;
    float* y = (float*)p_y;
    u64* wk2f2 = (u64*)p_wk;
    __nv_bfloat16* whi = (__nv_bfloat16*)p_hi;
    __nv_bfloat16* wlo = (__nv_bfloat16*)p_lo;

    const int SMEM_EDGE = 32768 + 16384;
    cudaFuncSetAttribute(gemm_mma<true, true, 0>,
                         cudaFuncAttributeMaxDynamicSharedMemorySize, SM_TOTAL);
    cudaFuncSetAttribute(gemm_mma<false, false, 1>,
                         cudaFuncAttributeMaxDynamicSharedMemorySize, SM_TOTAL);
    cudaFuncSetAttribute(gemm_mma<true, false, 2>,
                         cudaFuncAttributeMaxDynamicSharedMemorySize, SM_TOTAL);
    cudaFuncSetAttribute(edge_f2,
                         cudaFuncAttributeMaxDynamicSharedMemorySize, SMEM_EDGE);

    // one-time weight packing
    dim3 pw(64, 9);
    packw_kernel<<<pw, 256>>>(Wi, Wj, Wr1, Wr2, Wf, whi, wlo);
    pack_kernel<<<16, 256>>>(Wk2f, wk2f2, 32);

    int gemm_blocks = (N_ + 127) / 128;     // 391
    int edge_blocks = (E_ + 511) / 512;

    // m = xi = ssp(ssp(x) @ Wi + bi)
    gemm_mma<true, true, 0><<<gemm_blocks, 256, SM_TOTAL>>>(
        x, whi + 0 * 16384, wlo + 0 * 16384, bi, m, nullptr, nullptr, N_);
    // xjall = ssp(ssp(x) @ Wj + bj)
    gemm_mma<true, true, 0><<<gemm_blocks, 256, SM_TOTAL>>>(
        x, whi + 1 * 16384, wlo + 1 * 16384, bj, xjall, nullptr, nullptr, N_);
    // m += segment_sum(g * xjall[idx_j], idx_i)
    edge_f2<<<edge_blocks, 256, SMEM_EDGE>>>(rbf, wk2f2, xjall, idx_i, idx_j, m);

    // residual blocks
    for (int l = 0; l < L_; ++l) {
        gemm_mma<true, true, 0><<<gemm_blocks, 256, SM_TOTAL>>>(
            m, whi + (2 + l) * 16384, wlo + (2 + l) * 16384,
            br1 + (size_t)l * F_, y, nullptr, nullptr, N_);
        gemm_mma<false, false, 1><<<gemm_blocks, 256, SM_TOTAL>>>(
            y, whi + (5 + l) * 16384, wlo + (5 + l) * 16384,
            br2 + (size_t)l * F_, m, nullptr, nullptr, N_);
    }

    // out = u * x + ssp(m) @ Wf + bf
    gemm_mma<true, false, 2><<<gemm_blocks, 256, SM_TOTAL>>>(
        m, whi + 8 * 16384, wlo + 8 * 16384, bfb, out, x, u, N_);
}

// round 7
// speedup vs baseline: 2.9602x; 1.2044x over previous
#include <cuda_runtime.h>
#include <cuda_bf16.h>
#include <cstdint>

#define N_ 50000
#define F_ 128
#define E_ 800000
#define K_ 64
#define L_ 3

using u64 = unsigned long long;

// ---------------------------------------------------------------------------
// Scratch (static device globals — no runtime allocation)
// ---------------------------------------------------------------------------
__device__ float g_m[(size_t)N_ * F_];      // xi, then m (edge kernel adds into it)
__device__ float g_xjall[(size_t)N_ * F_];  // ssp(xa@Wj+bj)
__device__ float g_y[(size_t)N_ * F_];      // residual temp
__device__ u64 g_wk2f2[32 * 128];           // k-split packed Wk2f (edge kernel)
// bf16-split transposed node weights: [mat 0..8][c 0..127][k 0..127]
__device__ __nv_bfloat16 g_wthi[9 * 128 * 128];
__device__ __nv_bfloat16 g_wtlo[9 * 128 * 128];

__device__ __forceinline__ float ssp(float v) {
    // softplus(v) - ln2 via fast MUFU path; abs err ~1e-7 (fine vs 1e-3 gate)
    float ax = fabsf(v);
    return fmaxf(v, 0.0f) + __logf(1.0f + __expf(-ax)) -
           0.69314718055994530942f;
}
__device__ __forceinline__ float4 ssp4(float4 v) {
    v.x = ssp(v.x); v.y = ssp(v.y); v.z = ssp(v.z); v.w = ssp(v.w);
    return v;
}

__device__ __forceinline__ u64 ffma2(u64 a, u64 b, u64 c) {
    u64 d;
    asm("fma.rn.f32x2 %0, %1, %2, %3;" : "=l"(d) : "l"(a), "l"(b), "l"(c));
    return d;
}
__device__ __forceinline__ float lo32(u64 v) { return __uint_as_float((unsigned)v); }
__device__ __forceinline__ float hi32(u64 v) { return __uint_as_float((unsigned)(v >> 32)); }
__device__ __forceinline__ float pairsum(u64 v) { return lo32(v) + hi32(v); }

__device__ __forceinline__ uint32_t smem_u32(const void* p) {
    uint32_t a;
    asm("{ .reg .u64 t; cvta.to.shared.u64 t, %1; cvt.u32.u64 %0, t; }"
        : "=r"(a) : "l"(p));
    return a;
}

// ldmatrix x4 (non-transposed), b16
__device__ __forceinline__ void ldsm4(unsigned* r, uint32_t addr) {
    asm volatile(
        "ldmatrix.sync.aligned.m8n8.x4.shared.b16 {%0,%1,%2,%3}, [%4];"
        : "=r"(r[0]), "=r"(r[1]), "=r"(r[2]), "=r"(r[3]) : "r"(addr));
}

// mma m16n8k16 bf16 -> f32, accumulate in place
__device__ __forceinline__ void mma16816(float* d, const unsigned* a,
                                         const unsigned b0, const unsigned b1) {
    asm volatile(
        "mma.sync.aligned.m16n8k16.row.col.f32.bf16.bf16.f32 "
        "{%0,%1,%2,%3}, {%4,%5,%6,%7}, {%8,%9}, {%0,%1,%2,%3};"
        : "+f"(d[0]), "+f"(d[1]), "+f"(d[2]), "+f"(d[3])
        : "r"(a[0]), "r"(a[1]), "r"(a[2]), "r"(a[3]), "r"(b0), "r"(b1));
}

// ---------------------------------------------------------------------------
// Pack node weights: W[k][c] fp32 -> WT_hi/lo[c][k] bf16 (one launch, 9 mats)
// ---------------------------------------------------------------------------
__global__ void packw_kernel(const float* __restrict__ Wi,
                             const float* __restrict__ Wj,
                             const float* __restrict__ Wr1,
                             const float* __restrict__ Wr2,
                             const float* __restrict__ Wf,
                             __nv_bfloat16* __restrict__ hi,
                             __nv_bfloat16* __restrict__ lo) {
    int m = blockIdx.y;
    const float* W;
    if (m == 0) W = Wi;
    else if (m == 1) W = Wj;
    else if (m < 5) W = Wr1 + (size_t)(m - 2) * F_ * F_;
    else if (m < 8) W = Wr2 + (size_t)(m - 5) * F_ * F_;
    else W = Wf;
    int i = blockIdx.x * blockDim.x + threadIdx.x;
    if (i < 128 * 128) {
        int c = i >> 7, k = i & 127;
        float f = W[k * 128 + c];
        __nv_bfloat16 h = __float2bfloat16_rn(f);
        __nv_bfloat16 l = __float2bfloat16_rn(f - __bfloat162float(h));
        hi[(size_t)m * 16384 + i] = h;
        lo[(size_t)m * 16384 + i] = l;
    }
}

// pack Wk2f (k-split pairs for the edge kernel)
__global__ void pack_kernel(const float* __restrict__ W, u64* __restrict__ out,
                            int halfK) {
    int i = blockIdx.x * blockDim.x + threadIdx.x;
    if (i < halfK * 128) {
        int k2 = i >> 7, c = i & 127;
        unsigned lo = __float_as_uint(W[(2 * k2) * 128 + c]);
        unsigned hi = __float_as_uint(W[(2 * k2 + 1) * 128 + c]);
        out[i] = ((u64)hi << 32) | lo;
    }
}

// ---------------------------------------------------------------------------
// mma.sync node GEMM: C = ep( [ssp?](A) @ W + bias ), 64x128x128 tiles.
// 2-term bf16 split: D = Ahi*Whi + Ahi*Wlo + Alo*Whi (fp32 accum).
// 256 threads / 8 warps: warp = 16 rows x 64 cols (1 m16 x 8 n8 tiles).
// Smem 102KB -> 2 CTAs/SM for staging/MMA overlap.
// EP: 0 -> r, 1 -> C+r, 2 -> u*x + r
// ---------------------------------------------------------------------------
#define LDA 136
#define APLANE (64 * LDA * 2)      // 17408 B
#define WPLANE (128 * LDA * 2)     // 34816 B
#define SM_AHI 0
#define SM_ALO (SM_AHI + APLANE)
#define SM_WHI (SM_ALO + APLANE)
#define SM_WLO (SM_WHI + WPLANE)
#define SM_TOTAL (SM_WLO + WPLANE) // 104448 B -> 2 CTAs/SM

template <bool IN_ACT, bool OUT_ACT, int EP>
__global__ __launch_bounds__(256, 2)
void gemm_mma(const float* __restrict__ A,
              const __nv_bfloat16* __restrict__ wthi,
              const __nv_bfloat16* __restrict__ wtlo,
              const float* __restrict__ bias, float* __restrict__ C,
              const float* __restrict__ x, const float* __restrict__ u,
              int n) {
    extern __shared__ __align__(16) char sm[];
    uint32_t smb = smem_u32(sm);
    int tid = threadIdx.x;
    int wid = tid >> 5;
    int lane = tid & 31;
    int row0 = blockIdx.x * 64;

    // stage W hi/lo: [c][k] row-major -> [128][LDA] padded (2048 uint4/plane)
    {
        const uint4* srcH = reinterpret_cast<const uint4*>(wthi);
        const uint4* srcL = reinterpret_cast<const uint4*>(wtlo);
#pragma unroll
        for (int it = 0; it < 8; ++it) {
            int idx = tid + it * 256;      // 0..2047
            int row = idx >> 4;
            int seg = idx & 15;
            uint32_t off = (uint32_t)(row * LDA + seg * 8) * 2;
            *reinterpret_cast<uint4*>(sm + SM_WHI + off) = srcH[idx];
            *reinterpret_cast<uint4*>(sm + SM_WLO + off) = srcL[idx];
        }
    }
    // stage A hi/lo: fp32 -> ssp? -> bf16 split (64 rows, 2048 float4)
    {
        const float4* A4 = reinterpret_cast<const float4*>(A);
#pragma unroll
        for (int it = 0; it < 8; ++it) {
            int idx = tid + it * 256;      // 0..2047
            int row = idx >> 5;            // 0..63
            int k4 = idx & 31;
            float4 v = make_float4(0.f, 0.f, 0.f, 0.f);
            if (row0 + row < n) v = A4[(size_t)(row0 + row) * 32 + k4];
            if (IN_ACT) v = ssp4(v);
            __nv_bfloat162 h01 = __floats2bfloat162_rn(v.x, v.y);
            __nv_bfloat162 h23 = __floats2bfloat162_rn(v.z, v.w);
            __nv_bfloat162 l01 = __floats2bfloat162_rn(
                v.x - __bfloat162float(h01.x), v.y - __bfloat162float(h01.y));
            __nv_bfloat162 l23 = __floats2bfloat162_rn(
                v.z - __bfloat162float(h23.x), v.w - __bfloat162float(h23.y));
            uint32_t off = (uint32_t)(row * LDA + k4 * 4) * 2;
            u64 hv = ((u64)*reinterpret_cast<uint32_t*>(&h23) << 32) |
                     *reinterpret_cast<uint32_t*>(&h01);
            u64 lv = ((u64)*reinterpret_cast<uint32_t*>(&l23) << 32) |
                     *reinterpret_cast<uint32_t*>(&l01);
            *reinterpret_cast<u64*>(sm + SM_AHI + off) = hv;
            *reinterpret_cast<u64*>(sm + SM_ALO + off) = lv;
        }
    }
    __syncthreads();

    int warp_m = wid & 3;        // 4 row groups x 16 rows
    int warp_n = wid >> 2;       // 2 col groups x 64 cols

    float d[8][4];
#pragma unroll
    for (int nt = 0; nt < 8; ++nt)
#pragma unroll
        for (int q = 0; q < 4; ++q) d[nt][q] = 0.f;

    // per-lane ldmatrix offsets
    int a_row = warp_m * 16 + (lane & 15);
    int a_k8 = (lane >> 4) * 8;
    int b_n = warp_n * 64 + (lane >> 4) * 8 + (lane & 7);
    int b_k8 = ((lane >> 3) & 1) * 8;

#pragma unroll
    for (int ks = 0; ks < 8; ++ks) {
        int kb = ks * 16;
        unsigned bh[4][4], bl[4][4], ah[4], al[4];
#pragma unroll
        for (int p = 0; p < 4; ++p) {
            uint32_t boff = (uint32_t)((b_n + p * 16) * LDA + kb + b_k8) * 2;
            ldsm4(bh[p], smb + SM_WHI + boff);
            ldsm4(bl[p], smb + SM_WLO + boff);
        }
        {
            uint32_t aoff = (uint32_t)(a_row * LDA + kb + a_k8) * 2;
            ldsm4(ah, smb + SM_AHI + aoff);
            ldsm4(al, smb + SM_ALO + aoff);
        }
#pragma unroll
        for (int nt = 0; nt < 8; ++nt) {
            unsigned bh0 = bh[nt >> 1][(nt & 1) * 2];
            unsigned bh1 = bh[nt >> 1][(nt & 1) * 2 + 1];
            unsigned bl0 = bl[nt >> 1][(nt & 1) * 2];
            unsigned bl1 = bl[nt >> 1][(nt & 1) * 2 + 1];
            mma16816(d[nt], ah, bh0, bh1);
            mma16816(d[nt], ah, bl0, bl1);
            mma16816(d[nt], al, bh0, bh1);
        }
    }

    // epilogue: d0,d1 -> (r, c), d2,d3 -> (r+8, c); c = 2*(lane%4) in n8 tile
    const float2* bias2 = reinterpret_cast<const float2*>(bias);
    float2* C2 = reinterpret_cast<float2*>(C);
    const float2* x2 = reinterpret_cast<const float2*>(x);
    const float2* u2 = reinterpret_cast<const float2*>(u);

#pragma unroll
    for (int half = 0; half < 2; ++half) {
        int r = row0 + warp_m * 16 + (lane >> 2) + half * 8;
        if (r >= n) continue;
#pragma unroll
        for (int nt = 0; nt < 8; ++nt) {
            int c = warp_n * 64 + nt * 8 + (lane & 3) * 2;
            int ci = c >> 1;
            float2 bb = bias2[ci];
            float2 v;
            v.x = d[nt][half * 2 + 0] + bb.x;
            v.y = d[nt][half * 2 + 1] + bb.y;
            size_t gi = (size_t)r * 64 + ci;
            if constexpr (EP == 1) {
                float2 o = C2[gi];
                v.x += o.x; v.y += o.y;
            }
            if constexpr (EP == 2) {
                float2 xv = x2[gi];
                float2 uv = u2[ci];
                v.x += uv.x * xv.x; v.y += uv.y * xv.y;
            }
            if constexpr (OUT_ACT) { v.x = ssp(v.x); v.y = ssp(v.y); }
            C2[gi] = v;
        }
    }
}

// ---------------------------------------------------------------------------
// Edge kernel (f32x2, k-split, register-blocked over edges) — unchanged.
// ---------------------------------------------------------------------------
__global__ __launch_bounds__(256, 2)
void edge_f2(const float* __restrict__ rbf, const u64* __restrict__ Wt2,
             const float* __restrict__ xjall, const int* __restrict__ ii,
             const int* __restrict__ jj, float* __restrict__ mout) {
    extern __shared__ __align__(16) char smraw[];
    u64* Ws = reinterpret_cast<u64*>(smraw);               // 32KB
    float* rs = reinterpret_cast<float*>(smraw + 32768);   // 16KB

    int tid = threadIdx.x;
    {
        const ulonglong2* src = reinterpret_cast<const ulonglong2*>(Wt2);
        ulonglong2* dst = reinterpret_cast<ulonglong2*>(Ws);
#pragma unroll
        for (int i = 0; i < 8; ++i) dst[tid + i * 256] = src[tid + i * 256];
    }

    int tx = tid & 31;
    int eg = tid >> 5;
    int c0 = tx * 4;
    long base = (long)blockIdx.x * 512;

    const float4* rbf4 = reinterpret_cast<const float4*>(rbf);
    float4* rs4 = reinterpret_cast<float4*>(rs);
    const ulonglong2* rs2 = reinterpret_cast<const ulonglong2*>(rs);
    const ulonglong2* Ws2 = reinterpret_cast<const ulonglong2*>(Ws);

    int cur_i = -1;
    float racc[4] = {0.f, 0.f, 0.f, 0.f};

    for (int t = 0; t < 8; ++t) {
        __syncthreads();
#pragma unroll
        for (int s = 0; s < 4; ++s) {
            int idx = tid + s * 256;
            int er = idx >> 4;
            int k4 = idx & 15;
            long e = base + t * 64 + er;
            float4 v = make_float4(0.f, 0.f, 0.f, 0.f);
            if (e < E_) v = rbf4[e * 16 + k4];
            rs4[er * 16 + k4] = v;
        }
        __syncthreads();

        u64 acc[8][4];
#pragma unroll
        for (int el = 0; el < 8; ++el)
#pragma unroll
            for (int j = 0; j < 4; ++j) acc[el][j] = 0ull;

#pragma unroll 2
        for (int kk = 0; kk < 16; ++kk) {
            ulonglong2 wa0 = Ws2[(2 * kk) * 64 + tx * 2];
            ulonglong2 wa1 = Ws2[(2 * kk) * 64 + tx * 2 + 1];
            ulonglong2 wb0 = Ws2[(2 * kk + 1) * 64 + tx * 2];
            ulonglong2 wb1 = Ws2[(2 * kk + 1) * 64 + tx * 2 + 1];
#pragma unroll
            for (int el = 0; el < 8; ++el) {
                ulonglong2 a = rs2[(eg * 8 + el) * 16 + kk];
                acc[el][0] = ffma2(a.x, wa0.x, acc[el][0]);
                acc[el][1] = ffma2(a.x, wa0.y, acc[el][1]);
                acc[el][2] = ffma2(a.x, wa1.x, acc[el][2]);
                acc[el][3] = ffma2(a.x, wa1.y, acc[el][3]);
                acc[el][0] = ffma2(a.y, wb0.x, acc[el][0]);
                acc[el][1] = ffma2(a.y, wb0.y, acc[el][1]);
                acc[el][2] = ffma2(a.y, wb1.x, acc[el][2]);
                acc[el][3] = ffma2(a.y, wb1.y, acc[el][3]);
            }
        }

#pragma unroll
        for (int el = 0; el < 8; ++el) {
            long e = base + t * 64 + eg * 8 + el;
            if (e >= E_) break;
            int i = __ldg(ii + e);
            int j = __ldg(jj + e);
            float4 xv = __ldg(reinterpret_cast<const float4*>(
                                  xjall + (size_t)j * 128) + tx);
            float v0 = pairsum(acc[el][0]) * xv.x;
            float v1 = pairsum(acc[el][1]) * xv.y;
            float v2 = pairsum(acc[el][2]) * xv.z;
            float v3 = pairsum(acc[el][3]) * xv.w;
            if (i != cur_i) {
                if (cur_i >= 0) {
                    float* dst = mout + (size_t)cur_i * 128 + c0;
                    atomicAdd(dst + 0, racc[0]);
                    atomicAdd(dst + 1, racc[1]);
                    atomicAdd(dst + 2, racc[2]);
                    atomicAdd(dst + 3, racc[3]);
                }
                cur_i = i;
                racc[0] = v0; racc[1] = v1; racc[2] = v2; racc[3] = v3;
            } else {
                racc[0] += v0; racc[1] += v1; racc[2] += v2; racc[3] += v3;
            }
        }
    }
    if (cur_i >= 0) {
        float* dst = mout + (size_t)cur_i * 128 + c0;
        atomicAdd(dst + 0, racc[0]);
        atomicAdd(dst + 1, racc[1]);
        atomicAdd(dst + 2, racc[2]);
        atomicAdd(dst + 3, racc[3]);
    }
}

// ---------------------------------------------------------------------------
// Launch
// ---------------------------------------------------------------------------
extern "C" void kernel_launch(void* const* d_in, const int* in_sizes, int n_in,
                              void* d_out, int out_size) {
    const float* x    = (const float*)d_in[0];
    const float* rbf  = (const float*)d_in[1];
    const float* Wk2f = (const float*)d_in[2];
    const float* Wi   = (const float*)d_in[3];
    const float* bi   = (const float*)d_in[4];
    const float* Wj   = (const float*)d_in[5];
    const float* bj   = (const float*)d_in[6];
    const float* Wr1  = (const float*)d_in[7];
    const float* br1  = (const float*)d_in[8];
    const float* Wr2  = (const float*)d_in[9];
    const float* br2  = (const float*)d_in[10];
    const float* Wf   = (const float*)d_in[11];
    const float* bfb  = (const float*)d_in[12];
    const float* u    = (const float*)d_in[13];
    const int* idx_i  = (const int*)d_in[14];
    const int* idx_j  = (const int*)d_in[15];
    float* out = (float*)d_out;

    void *p_m, *p_xjall, *p_y, *p_wk, *p_hi, *p_lo;
    cudaGetSymbolAddress(&p_m, g_m);
    cudaGetSymbolAddress(&p_xjall, g_xjall);
    cudaGetSymbolAddress(&p_y, g_y);
    cudaGetSymbolAddress(&p_wk, g_wk2f2);
    cudaGetSymbolAddress(&p_hi, g_wthi);
    cudaGetSymbolAddress(&p_lo, g_wtlo);
    float* m = (float*)p_m;
    float* xjall = (float*)p_xjall;
    float* y = (float*)p_y;
    u64* wk2f2 = (u64*)p_wk;
    __nv_bfloat16* whi = (__nv_bfloat16*)p_hi;
    __nv_bfloat16* wlo = (__nv_bfloat16*)p_lo;

    const int SMEM_EDGE = 32768 + 16384;
    cudaFuncSetAttribute(gemm_mma<true, true, 0>,
                         cudaFuncAttributeMaxDynamicSharedMemorySize, SM_TOTAL);
    cudaFuncSetAttribute(gemm_mma<false, false, 1>,
                         cudaFuncAttributeMaxDynamicSharedMemorySize, SM_TOTAL);
    cudaFuncSetAttribute(gemm_mma<true, false, 2>,
                         cudaFuncAttributeMaxDynamicSharedMemorySize, SM_TOTAL);
    cudaFuncSetAttribute(edge_f2,
                         cudaFuncAttributeMaxDynamicSharedMemorySize, SMEM_EDGE);

    // one-time weight packing
    dim3 pw(64, 9);
    packw_kernel<<<pw, 256>>>(Wi, Wj, Wr1, Wr2, Wf, whi, wlo);
    pack_kernel<<<16, 256>>>(Wk2f, wk2f2, 32);

    int gemm_blocks = (N_ + 63) / 64;       // 782
    int edge_blocks = (E_ + 511) / 512;

    // m = xi = ssp(ssp(x) @ Wi + bi)
    gemm_mma<true, true, 0><<<gemm_blocks, 256, SM_TOTAL>>>(
        x, whi + 0 * 16384, wlo + 0 * 16384, bi, m, nullptr, nullptr, N_);
    // xjall = ssp(ssp(x) @ Wj + bj)
    gemm_mma<true, true, 0><<<gemm_blocks, 256, SM_TOTAL>>>(
        x, whi + 1 * 16384, wlo + 1 * 16384, bj, xjall, nullptr, nullptr, N_);
    // m += segment_sum(g * xjall[idx_j], idx_i)
    edge_f2<<<edge_blocks, 256, SMEM_EDGE>>>(rbf, wk2f2, xjall, idx_i, idx_j, m);

    // residual blocks
    for (int l = 0; l < L_; ++l) {
        gemm_mma<true, true, 0><<<gemm_blocks, 256, SM_TOTAL>>>(
            m, whi + (2 + l) * 16384, wlo + (2 + l) * 16384,
            br1 + (size_t)l * F_, y, nullptr, nullptr, N_);
        gemm_mma<false, false, 1><<<gemm_blocks, 256, SM_TOTAL>>>(
            y, whi + (5 + l) * 16384, wlo + (5 + l) * 16384,
            br2 + (size_t)l * F_, m, nullptr, nullptr, N_);
    }

    // out = u * x + ssp(m) @ Wf + bf
    gemm_mma<true, false, 2><<<gemm_blocks, 256, SM_TOTAL>>>(
        m, whi + 8 * 16384, wlo + 8 * 16384, bfb, out, x, u, N_);
}

// round 8
// speedup vs baseline: 3.6719x; 1.2404x over previous
#include <cuda_runtime.h>
#include <cuda_bf16.h>
#include <cstdint>

#define N_ 50000
#define F_ 128
#define E_ 800000
#define K_ 64
#define L_ 3

using u64 = unsigned long long;

// ---------------------------------------------------------------------------
// Scratch (static device globals — no runtime allocation)
// ---------------------------------------------------------------------------
__device__ float g_m[(size_t)N_ * F_];      // xi, then m (edge kernel adds into it)
__device__ float g_xjall[(size_t)N_ * F_];  // ssp(xa@Wj+bj)
__device__ float g_y[(size_t)N_ * F_];      // residual temp
// bf16-split transposed node weights: [mat 0..8][c 0..127][k 0..127]
__device__ __nv_bfloat16 g_wthi[9 * 128 * 128];
__device__ __nv_bfloat16 g_wtlo[9 * 128 * 128];
// bf16-split transposed Wk2f: [c 0..127][k 0..63]
__device__ __nv_bfloat16 g_wkhi[128 * 64];
__device__ __nv_bfloat16 g_wklo[128 * 64];

__device__ __forceinline__ float ssp(float v) {
    // softplus(v) - ln2 via fast MUFU path; abs err ~1e-7
    float ax = fabsf(v);
    return fmaxf(v, 0.0f) + __logf(1.0f + __expf(-ax)) -
           0.69314718055994530942f;
}
__device__ __forceinline__ float4 ssp4(float4 v) {
    v.x = ssp(v.x); v.y = ssp(v.y); v.z = ssp(v.z); v.w = ssp(v.w);
    return v;
}

__device__ __forceinline__ uint32_t smem_u32(const void* p) {
    uint32_t a;
    asm("{ .reg .u64 t; cvta.to.shared.u64 t, %1; cvt.u32.u64 %0, t; }"
        : "=r"(a) : "l"(p));
    return a;
}

// ldmatrix x4 (non-transposed), b16
__device__ __forceinline__ void ldsm4(unsigned* r, uint32_t addr) {
    asm volatile(
        "ldmatrix.sync.aligned.m8n8.x4.shared.b16 {%0,%1,%2,%3}, [%4];"
        : "=r"(r[0]), "=r"(r[1]), "=r"(r[2]), "=r"(r[3]) : "r"(addr));
}

// mma m16n8k16 bf16 -> f32, accumulate in place
__device__ __forceinline__ void mma16816(float* d, const unsigned* a,
                                         const unsigned b0, const unsigned b1) {
    asm volatile(
        "mma.sync.aligned.m16n8k16.row.col.f32.bf16.bf16.f32 "
        "{%0,%1,%2,%3}, {%4,%5,%6,%7}, {%8,%9}, {%0,%1,%2,%3};"
        : "+f"(d[0]), "+f"(d[1]), "+f"(d[2]), "+f"(d[3])
        : "r"(a[0]), "r"(a[1]), "r"(a[2]), "r"(a[3]), "r"(b0), "r"(b1));
}

// ---------------------------------------------------------------------------
// Pack node weights: W[k][c] fp32 -> WT_hi/lo[c][k] bf16 (one launch, 9 mats)
// ---------------------------------------------------------------------------
__global__ void packw_kernel(const float* __restrict__ Wi,
                             const float* __restrict__ Wj,
                             const float* __restrict__ Wr1,
                             const float* __restrict__ Wr2,
                             const float* __restrict__ Wf,
                             __nv_bfloat16* __restrict__ hi,
                             __nv_bfloat16* __restrict__ lo) {
    int m = blockIdx.y;
    const float* W;
    if (m == 0) W = Wi;
    else if (m == 1) W = Wj;
    else if (m < 5) W = Wr1 + (size_t)(m - 2) * F_ * F_;
    else if (m < 8) W = Wr2 + (size_t)(m - 5) * F_ * F_;
    else W = Wf;
    int i = blockIdx.x * blockDim.x + threadIdx.x;
    if (i < 128 * 128) {
        int c = i >> 7, k = i & 127;
        float f = W[k * 128 + c];
        __nv_bfloat16 h = __float2bfloat16_rn(f);
        __nv_bfloat16 l = __float2bfloat16_rn(f - __bfloat162float(h));
        hi[(size_t)m * 16384 + i] = h;
        lo[(size_t)m * 16384 + i] = l;
    }
}

// Pack Wk2f: [k 0..63][c 0..127] fp32 -> [c][k] hi/lo bf16
__global__ void packwk_kernel(const float* __restrict__ W,
                              __nv_bfloat16* __restrict__ hi,
                              __nv_bfloat16* __restrict__ lo) {
    int i = blockIdx.x * blockDim.x + threadIdx.x;
    if (i < 128 * 64) {
        int c = i >> 6, k = i & 63;
        float f = W[k * 128 + c];
        __nv_bfloat16 h = __float2bfloat16_rn(f);
        __nv_bfloat16 l = __float2bfloat16_rn(f - __bfloat162float(h));
        hi[i] = h;
        lo[i] = l;
    }
}

// ---------------------------------------------------------------------------
// mma.sync node GEMM: C = ep( [ssp?](A) @ W + bias ), 64x128x128 tiles.
// 2-term bf16 split: D = Ahi*Whi + Ahi*Wlo + Alo*Whi (fp32 accum).
// 256 threads / 8 warps in 2x4 grid: warp = 32 rows x 32 cols
// (2 m16 x 4 n8 tiles) -> 8 LDSM per 24 HMMA.
// EP: 0 -> r, 1 -> C+r, 2 -> u*x + r
// ---------------------------------------------------------------------------
#define LDA 136
#define APLANE (64 * LDA * 2)      // 17408 B
#define WPLANE (128 * LDA * 2)     // 34816 B
#define SM_AHI 0
#define SM_ALO (SM_AHI + APLANE)
#define SM_WHI (SM_ALO + APLANE)
#define SM_WLO (SM_WHI + WPLANE)
#define SM_TOTAL (SM_WLO + WPLANE) // 104448 B -> 2 CTAs/SM

template <bool IN_ACT, bool OUT_ACT, int EP>
__global__ __launch_bounds__(256, 2)
void gemm_mma(const float* __restrict__ A,
              const __nv_bfloat16* __restrict__ wthi,
              const __nv_bfloat16* __restrict__ wtlo,
              const float* __restrict__ bias, float* __restrict__ C,
              const float* __restrict__ x, const float* __restrict__ u,
              int n) {
    extern __shared__ __align__(16) char sm[];
    uint32_t smb = smem_u32(sm);
    int tid = threadIdx.x;
    int wid = tid >> 5;
    int lane = tid & 31;
    int row0 = blockIdx.x * 64;

    // stage W hi/lo: [c][k] row-major -> [128][LDA] padded (2048 uint4/plane)
    {
        const uint4* srcH = reinterpret_cast<const uint4*>(wthi);
        const uint4* srcL = reinterpret_cast<const uint4*>(wtlo);
#pragma unroll
        for (int it = 0; it < 8; ++it) {
            int idx = tid + it * 256;      // 0..2047
            int row = idx >> 4;
            int seg = idx & 15;
            uint32_t off = (uint32_t)(row * LDA + seg * 8) * 2;
            *reinterpret_cast<uint4*>(sm + SM_WHI + off) = srcH[idx];
            *reinterpret_cast<uint4*>(sm + SM_WLO + off) = srcL[idx];
        }
    }
    // stage A hi/lo: fp32 -> ssp? -> bf16 split (64 rows, 2048 float4)
    {
        const float4* A4 = reinterpret_cast<const float4*>(A);
#pragma unroll
        for (int it = 0; it < 8; ++it) {
            int idx = tid + it * 256;      // 0..2047
            int row = idx >> 5;            // 0..63
            int k4 = idx & 31;
            float4 v = make_float4(0.f, 0.f, 0.f, 0.f);
            if (row0 + row < n) v = A4[(size_t)(row0 + row) * 32 + k4];
            if (IN_ACT) v = ssp4(v);
            __nv_bfloat162 h01 = __floats2bfloat162_rn(v.x, v.y);
            __nv_bfloat162 h23 = __floats2bfloat162_rn(v.z, v.w);
            __nv_bfloat162 l01 = __floats2bfloat162_rn(
                v.x - __bfloat162float(h01.x), v.y - __bfloat162float(h01.y));
            __nv_bfloat162 l23 = __floats2bfloat162_rn(
                v.z - __bfloat162float(h23.x), v.w - __bfloat162float(h23.y));
            uint32_t off = (uint32_t)(row * LDA + k4 * 4) * 2;
            u64 hv = ((u64)*reinterpret_cast<uint32_t*>(&h23) << 32) |
                     *reinterpret_cast<uint32_t*>(&h01);
            u64 lv = ((u64)*reinterpret_cast<uint32_t*>(&l23) << 32) |
                     *reinterpret_cast<uint32_t*>(&l01);
            *reinterpret_cast<u64*>(sm + SM_AHI + off) = hv;
            *reinterpret_cast<u64*>(sm + SM_ALO + off) = lv;
        }
    }
    __syncthreads();

    int warp_m = wid & 1;        // 2 row groups x 32 rows
    int warp_n = wid >> 1;       // 4 col groups x 32 cols

    float d[2][4][4];
#pragma unroll
    for (int mt = 0; mt < 2; ++mt)
#pragma unroll
        for (int nt = 0; nt < 4; ++nt)
#pragma unroll
            for (int q = 0; q < 4; ++q) d[mt][nt][q] = 0.f;

    int a_row = warp_m * 32 + (lane & 15);
    int a_k8 = (lane >> 4) * 8;
    int b_n = warp_n * 32 + (lane >> 4) * 8 + (lane & 7);
    int b_k8 = ((lane >> 3) & 1) * 8;

#pragma unroll
    for (int ks = 0; ks < 8; ++ks) {
        int kb = ks * 16;
        unsigned bh[2][4], bl[2][4], ah[2][4], al[2][4];
#pragma unroll
        for (int p = 0; p < 2; ++p) {
            uint32_t boff = (uint32_t)((b_n + p * 16) * LDA + kb + b_k8) * 2;
            ldsm4(bh[p], smb + SM_WHI + boff);
            ldsm4(bl[p], smb + SM_WLO + boff);
        }
#pragma unroll
        for (int mt = 0; mt < 2; ++mt) {
            uint32_t aoff = (uint32_t)((a_row + mt * 16) * LDA + kb + a_k8) * 2;
            ldsm4(ah[mt], smb + SM_AHI + aoff);
            ldsm4(al[mt], smb + SM_ALO + aoff);
        }
#pragma unroll
        for (int mt = 0; mt < 2; ++mt) {
#pragma unroll
            for (int nt = 0; nt < 4; ++nt) {
                unsigned bh0 = bh[nt >> 1][(nt & 1) * 2];
                unsigned bh1 = bh[nt >> 1][(nt & 1) * 2 + 1];
                unsigned bl0 = bl[nt >> 1][(nt & 1) * 2];
                unsigned bl1 = bl[nt >> 1][(nt & 1) * 2 + 1];
                mma16816(d[mt][nt], ah[mt], bh0, bh1);
                mma16816(d[mt][nt], ah[mt], bl0, bl1);
                mma16816(d[mt][nt], al[mt], bh0, bh1);
            }
        }
    }

    // epilogue
    const float2* bias2 = reinterpret_cast<const float2*>(bias);
    float2* C2 = reinterpret_cast<float2*>(C);
    const float2* x2 = reinterpret_cast<const float2*>(x);
    const float2* u2 = reinterpret_cast<const float2*>(u);

#pragma unroll
    for (int mt = 0; mt < 2; ++mt) {
#pragma unroll
        for (int half = 0; half < 2; ++half) {
            int r = row0 + warp_m * 32 + mt * 16 + (lane >> 2) + half * 8;
            if (r >= n) continue;
#pragma unroll
            for (int nt = 0; nt < 4; ++nt) {
                int c = warp_n * 32 + nt * 8 + (lane & 3) * 2;
                int ci = c >> 1;
                float2 bb = bias2[ci];
                float2 v;
                v.x = d[mt][nt][half * 2 + 0] + bb.x;
                v.y = d[mt][nt][half * 2 + 1] + bb.y;
                size_t gi = (size_t)r * 64 + ci;
                if constexpr (EP == 1) {
                    float2 o = C2[gi];
                    v.x += o.x; v.y += o.y;
                }
                if constexpr (EP == 2) {
                    float2 xv = x2[gi];
                    float2 uv = u2[ci];
                    v.x += uv.x * xv.x; v.y += uv.y * xv.y;
                }
                if constexpr (OUT_ACT) { v.x = ssp(v.x); v.y = ssp(v.y); }
                C2[gi] = v;
            }
        }
    }
}

// ---------------------------------------------------------------------------
// Edge kernel, MMA version. Per 512-edge block, 8 tiles of 64 edges:
//   stage rbf tile -> bf16 hi/lo; MMA g = rbf @ Wk2f^T (3-term split);
//   dump g (fp32) to smem; sequential gather/gate/run-length-scatter.
// 89KB smem -> 2 CTAs/SM.
// ---------------------------------------------------------------------------
#define ELDK 72
#define EW_PLANE (128 * ELDK * 2)   // 18432
#define EA_PLANE (64 * ELDK * 2)    // 9216
#define EG_LD 132
#define ESM_WHI 0
#define ESM_WLO (ESM_WHI + EW_PLANE)
#define ESM_AHI (ESM_WLO + EW_PLANE)
#define ESM_ALO (ESM_AHI + EA_PLANE)
#define ESM_G   (ESM_ALO + EA_PLANE)
#define ESM_TOTAL (ESM_G + 64 * EG_LD * 4)   // 89088 B

__global__ __launch_bounds__(256, 2)
void edge_mma(const float* __restrict__ rbf,
              const __nv_bfloat16* __restrict__ wkhi,
              const __nv_bfloat16* __restrict__ wklo,
              const float* __restrict__ xjall, const int* __restrict__ ii,
              const int* __restrict__ jj, float* __restrict__ mout) {
    extern __shared__ __align__(16) char sm[];
    uint32_t smb = smem_u32(sm);
    int tid = threadIdx.x;
    int wid = tid >> 5;
    int lane = tid & 31;

    // stage W planes: [128 c][64 k] bf16, 1024 uint4 each
    {
        const uint4* srcH = reinterpret_cast<const uint4*>(wkhi);
        const uint4* srcL = reinterpret_cast<const uint4*>(wklo);
#pragma unroll
        for (int it = 0; it < 4; ++it) {
            int idx = tid + it * 256;      // 0..1023
            int row = idx >> 3;
            int seg = idx & 7;
            uint32_t off = (uint32_t)(row * ELDK + seg * 8) * 2;
            *reinterpret_cast<uint4*>(sm + ESM_WHI + off) = srcH[idx];
            *reinterpret_cast<uint4*>(sm + ESM_WLO + off) = srcL[idx];
        }
    }

    int warp_m = wid & 1;
    int warp_n = wid >> 1;
    int a_row = warp_m * 32 + (lane & 15);
    int a_k8 = (lane >> 4) * 8;
    int b_n = warp_n * 32 + (lane >> 4) * 8 + (lane & 7);
    int b_k8 = ((lane >> 3) & 1) * 8;

    int tx = tid & 31;      // col group: cols tx*4..tx*4+3
    int eg = tid >> 5;      // edge group of 8 within tile
    int c0 = tx * 4;
    long base = (long)blockIdx.x * 512;

    const float4* rbf4 = reinterpret_cast<const float4*>(rbf);

    int cur_i = -1;
    float racc[4] = {0.f, 0.f, 0.f, 0.f};

    for (int t = 0; t < 8; ++t) {
        __syncthreads();   // protect A and G reuse from previous tile
        // stage rbf tile: 64 edges x 64 k (1024 float4), split to bf16 hi/lo
#pragma unroll
        for (int s = 0; s < 4; ++s) {
            int idx = tid + s * 256;       // 0..1023
            int er = idx >> 4;             // 0..63
            int k4 = idx & 15;
            long e = base + t * 64 + er;
            float4 v = make_float4(0.f, 0.f, 0.f, 0.f);
            if (e < E_) v = rbf4[e * 16 + k4];
            __nv_bfloat162 h01 = __floats2bfloat162_rn(v.x, v.y);
            __nv_bfloat162 h23 = __floats2bfloat162_rn(v.z, v.w);
            __nv_bfloat162 l01 = __floats2bfloat162_rn(
                v.x - __bfloat162float(h01.x), v.y - __bfloat162float(h01.y));
            __nv_bfloat162 l23 = __floats2bfloat162_rn(
                v.z - __bfloat162float(h23.x), v.w - __bfloat162float(h23.y));
            uint32_t off = (uint32_t)(er * ELDK + k4 * 4) * 2;
            u64 hv = ((u64)*reinterpret_cast<uint32_t*>(&h23) << 32) |
                     *reinterpret_cast<uint32_t*>(&h01);
            u64 lv = ((u64)*reinterpret_cast<uint32_t*>(&l23) << 32) |
                     *reinterpret_cast<uint32_t*>(&l01);
            *reinterpret_cast<u64*>(sm + ESM_AHI + off) = hv;
            *reinterpret_cast<u64*>(sm + ESM_ALO + off) = lv;
        }
        __syncthreads();

        // MMA: g[64 e][128 c] = rbf @ Wk2f^T, 3-term split, K=64
        float d[2][4][4];
#pragma unroll
        for (int mt = 0; mt < 2; ++mt)
#pragma unroll
            for (int nt = 0; nt < 4; ++nt)
#pragma unroll
                for (int q = 0; q < 4; ++q) d[mt][nt][q] = 0.f;

#pragma unroll
        for (int ks = 0; ks < 4; ++ks) {
            int kb = ks * 16;
            unsigned bh[2][4], bl[2][4], ah[2][4], al[2][4];
#pragma unroll
            for (int p = 0; p < 2; ++p) {
                uint32_t boff =
                    (uint32_t)((b_n + p * 16) * ELDK + kb + b_k8) * 2;
                ldsm4(bh[p], smb + ESM_WHI + boff);
                ldsm4(bl[p], smb + ESM_WLO + boff);
            }
#pragma unroll
            for (int mt = 0; mt < 2; ++mt) {
                uint32_t aoff =
                    (uint32_t)((a_row + mt * 16) * ELDK + kb + a_k8) * 2;
                ldsm4(ah[mt], smb + ESM_AHI + aoff);
                ldsm4(al[mt], smb + ESM_ALO + aoff);
            }
#pragma unroll
            for (int mt = 0; mt < 2; ++mt) {
#pragma unroll
                for (int nt = 0; nt < 4; ++nt) {
                    unsigned bh0 = bh[nt >> 1][(nt & 1) * 2];
                    unsigned bh1 = bh[nt >> 1][(nt & 1) * 2 + 1];
                    unsigned bl0 = bl[nt >> 1][(nt & 1) * 2];
                    unsigned bl1 = bl[nt >> 1][(nt & 1) * 2 + 1];
                    mma16816(d[mt][nt], ah[mt], bh0, bh1);
                    mma16816(d[mt][nt], ah[mt], bl0, bl1);
                    mma16816(d[mt][nt], al[mt], bh0, bh1);
                }
            }
        }

        // dump g to smem (fp32, padded rows)
#pragma unroll
        for (int mt = 0; mt < 2; ++mt)
#pragma unroll
            for (int half = 0; half < 2; ++half) {
                int row = warp_m * 32 + mt * 16 + (lane >> 2) + half * 8;
#pragma unroll
                for (int nt = 0; nt < 4; ++nt) {
                    int col = warp_n * 32 + nt * 8 + (lane & 3) * 2;
                    float2 v;
                    v.x = d[mt][nt][half * 2 + 0];
                    v.y = d[mt][nt][half * 2 + 1];
                    *reinterpret_cast<float2*>(
                        sm + ESM_G + (uint32_t)(row * EG_LD + col) * 4) = v;
                }
            }
        __syncthreads();

        // epilogue: gather + gate + run-length scatter (idx_i sorted)
#pragma unroll
        for (int s = 0; s < 8; ++s) {
            long e = base + t * 64 + eg * 8 + s;
            if (e >= E_) continue;
            float4 g4 = *reinterpret_cast<const float4*>(
                sm + ESM_G + (uint32_t)((eg * 8 + s) * EG_LD + c0) * 4);
            int i = __ldg(ii + e);
            int j = __ldg(jj + e);
            float4 xv = __ldg(reinterpret_cast<const float4*>(
                                  xjall + (size_t)j * 128) + tx);
            float v0 = g4.x * xv.x;
            float v1 = g4.y * xv.y;
            float v2 = g4.z * xv.z;
            float v3 = g4.w * xv.w;
            if (i != cur_i) {
                if (cur_i >= 0) {
                    float* dst = mout + (size_t)cur_i * 128 + c0;
                    atomicAdd(dst + 0, racc[0]);
                    atomicAdd(dst + 1, racc[1]);
                    atomicAdd(dst + 2, racc[2]);
                    atomicAdd(dst + 3, racc[3]);
                }
                cur_i = i;
                racc[0] = v0; racc[1] = v1; racc[2] = v2; racc[3] = v3;
            } else {
                racc[0] += v0; racc[1] += v1; racc[2] += v2; racc[3] += v3;
            }
        }
    }
    if (cur_i >= 0) {
        float* dst = mout + (size_t)cur_i * 128 + c0;
        atomicAdd(dst + 0, racc[0]);
        atomicAdd(dst + 1, racc[1]);
        atomicAdd(dst + 2, racc[2]);
        atomicAdd(dst + 3, racc[3]);
    }
}

// ---------------------------------------------------------------------------
// Launch
// ---------------------------------------------------------------------------
extern "C" void kernel_launch(void* const* d_in, const int* in_sizes, int n_in,
                              void* d_out, int out_size) {
    const float* x    = (const float*)d_in[0];
    const float* rbf  = (const float*)d_in[1];
    const float* Wk2f = (const float*)d_in[2];
    const float* Wi   = (const float*)d_in[3];
    const float* bi   = (const float*)d_in[4];
    const float* Wj   = (const float*)d_in[5];
    const float* bj   = (const float*)d_in[6];
    const float* Wr1  = (const float*)d_in[7];
    const float* br1  = (const float*)d_in[8];
    const float* Wr2  = (const float*)d_in[9];
    const float* br2  = (const float*)d_in[10];
    const float* Wf   = (const float*)d_in[11];
    const float* bfb  = (const float*)d_in[12];
    const float* u    = (const float*)d_in[13];
    const int* idx_i  = (const int*)d_in[14];
    const int* idx_j  = (const int*)d_in[15];
    float* out = (float*)d_out;

    void *p_m, *p_xjall, *p_y, *p_hi, *p_lo, *p_wkh, *p_wkl;
    cudaGetSymbolAddress(&p_m, g_m);
    cudaGetSymbolAddress(&p_xjall, g_xjall);
    cudaGetSymbolAddress(&p_y, g_y);
    cudaGetSymbolAddress(&p_hi, g_wthi);
    cudaGetSymbolAddress(&p_lo, g_wtlo);
    cudaGetSymbolAddress(&p_wkh, g_wkhi);
    cudaGetSymbolAddress(&p_wkl, g_wklo);
    float* m = (float*)p_m;
    float* xjall = (float*)p_xjall;
    float* y = (float*)p_y;
    __nv_bfloat16* whi = (__nv_bfloat16*)p_hi;
    __nv_bfloat16* wlo = (__nv_bfloat16*)p_lo;
    __nv_bfloat16* wkhi = (__nv_bfloat16*)p_wkh;
    __nv_bfloat16* wklo = (__nv_bfloat16*)p_wkl;

    cudaFuncSetAttribute(gemm_mma<true, true, 0>,
                         cudaFuncAttributeMaxDynamicSharedMemorySize, SM_TOTAL);
    cudaFuncSetAttribute(gemm_mma<false, false, 1>,
                         cudaFuncAttributeMaxDynamicSharedMemorySize, SM_TOTAL);
    cudaFuncSetAttribute(gemm_mma<true, false, 2>,
                         cudaFuncAttributeMaxDynamicSharedMemorySize, SM_TOTAL);
    cudaFuncSetAttribute(edge_mma,
                         cudaFuncAttributeMaxDynamicSharedMemorySize, ESM_TOTAL);

    // one-time weight packing
    dim3 pw(64, 9);
    packw_kernel<<<pw, 256>>>(Wi, Wj, Wr1, Wr2, Wf, whi, wlo);
    packwk_kernel<<<32, 256>>>(Wk2f, wkhi, wklo);

    int gemm_blocks = (N_ + 63) / 64;       // 782
    int edge_blocks = (E_ + 511) / 512;     // 1563

    // m = xi = ssp(ssp(x) @ Wi + bi)
    gemm_mma<true, true, 0><<<gemm_blocks, 256, SM_TOTAL>>>(
        x, whi + 0 * 16384, wlo + 0 * 16384, bi, m, nullptr, nullptr, N_);
    // xjall = ssp(ssp(x) @ Wj + bj)
    gemm_mma<true, true, 0><<<gemm_blocks, 256, SM_TOTAL>>>(
        x, whi + 1 * 16384, wlo + 1 * 16384, bj, xjall, nullptr, nullptr, N_);
    // m += segment_sum((rbf@Wk2f) * xjall[idx_j], idx_i)
    edge_mma<<<edge_blocks, 256, ESM_TOTAL>>>(rbf, wkhi, wklo, xjall,
                                              idx_i, idx_j, m);

    // residual blocks
    for (int l = 0; l < L_; ++l) {
        gemm_mma<true, true, 0><<<gemm_blocks, 256, SM_TOTAL>>>(
            m, whi + (2 + l) * 16384, wlo + (2 + l) * 16384,
            br1 + (size_t)l * F_, y, nullptr, nullptr, N_);
        gemm_mma<false, false, 1><<<gemm_blocks, 256, SM_TOTAL>>>(
            y, whi + (5 + l) * 16384, wlo + (5 + l) * 16384,
            br2 + (size_t)l * F_, m, nullptr, nullptr, N_);
    }

    // out = u * x + ssp(m) @ Wf + bf
    gemm_mma<true, false, 2><<<gemm_blocks, 256, SM_TOTAL>>>(
        m, whi + 8 * 16384, wlo + 8 * 16384, bfb, out, x, u, N_);
}